// round 1
// baseline (speedup 1.0000x reference)
#include <cuda_runtime.h>
#include <cuda_bf16.h>

#define NU     100000
#define NI     50000
#define NN     150000          // NU + NI
#define DD     64
#define EMAX   3000000
#define LAYERS 3

// ---------------- static device scratch (no allocations allowed) ----------
__device__ int   g_deg[NN];
__device__ int   g_rowptr[NN + 1];
__device__ int   g_cursor[NN];
__device__ int   g_colidx[2 * EMAX];       // 24 MB
__device__ float g_dis[NN];
__device__ float g_h[NN * DD];             // h' = dis * h   (38.4 MB)
__device__ float g_agg[NN * DD];           // SpMM output    (38.4 MB)
__device__ float g_acc[NN * DD];           // running sum    (38.4 MB)

// ---------------- kernels -------------------------------------------------

__global__ void k_zero_deg() {
    int i = blockIdx.x * blockDim.x + threadIdx.x;
    if (i < NN) g_deg[i] = 0;
}

__global__ void k_hist(const int* __restrict__ ui, const int* __restrict__ ii, int E) {
    int e = blockIdx.x * blockDim.x + threadIdx.x;
    if (e < E) {
        atomicAdd(&g_deg[ui[e]], 1);
        atomicAdd(&g_deg[NU + ii[e]], 1);
    }
}

// single-block exclusive scan over g_deg -> g_rowptr / g_cursor, plus dis = rsqrt(deg)
__global__ void k_scan() {
    __shared__ int ssum[1024];
    int t = threadIdx.x;
    const int chunk = (NN + 1023) / 1024;           // 147
    int begin = t * chunk;
    int end   = begin + chunk; if (end > NN) end = NN;
    if (begin > NN) begin = NN;

    int s = 0;
    for (int i = begin; i < end; i++) s += g_deg[i];
    ssum[t] = s;
    __syncthreads();
    // inclusive Hillis-Steele scan
    for (int off = 1; off < 1024; off <<= 1) {
        int v = (t >= off) ? ssum[t - off] : 0;
        __syncthreads();
        ssum[t] += v;
        __syncthreads();
    }
    int run = (t == 0) ? 0 : ssum[t - 1];
    for (int i = begin; i < end; i++) {
        int d = g_deg[i];
        g_rowptr[i] = run;
        g_cursor[i] = run;
        g_dis[i]    = rsqrtf((float)d + 1e-10f);
        run += d;
    }
    if (t == 1023) g_rowptr[NN] = ssum[1023];
}

__global__ void k_scatter(const int* __restrict__ ui, const int* __restrict__ ii, int E) {
    int e = blockIdx.x * blockDim.x + threadIdx.x;
    if (e < E) {
        int u  = ui[e];
        int it = NU + ii[e];
        int p1 = atomicAdd(&g_cursor[u], 1);
        g_colidx[p1] = it;
        int p2 = atomicAdd(&g_cursor[it], 1);
        g_colidx[p2] = u;
    }
}

// acc = x ; h' = dis * x
__global__ void k_init(const float* __restrict__ ue, const float* __restrict__ ie) {
    int i = blockIdx.x * blockDim.x + threadIdx.x;
    if (i < NN * DD) {
        int n = i >> 6;
        float x = (n < NU) ? ue[i] : ie[i - NU * DD];
        g_acc[i] = x;
        g_h[i]   = g_dis[n] * x;
    }
}

// warp-per-row gather SpMM: agg[r] = sum_{c in adj(r)} h'[c]   (row dis applied later)
__global__ void __launch_bounds__(256) k_spmm() {
    int w    = (blockIdx.x * blockDim.x + threadIdx.x) >> 5;
    int lane = threadIdx.x & 31;
    if (w >= NN) return;

    int s = g_rowptr[w];
    int e = g_rowptr[w + 1];

    float2 a0 = make_float2(0.f, 0.f);
    float2 a1 = make_float2(0.f, 0.f);

    for (int base = s; base < e; base += 32) {
        int c = 0;
        int cnt = e - base; if (cnt > 32) cnt = 32;
        if (lane < cnt) c = g_colidx[base + lane];
        #pragma unroll 4
        for (int j = 0; j < cnt; j++) {
            int cc = __shfl_sync(0xffffffffu, c, j);
            float2 v = *(const float2*)(g_h + cc * DD + 2 * lane);
            if (j & 1) { a1.x += v.x; a1.y += v.y; }
            else       { a0.x += v.x; a0.y += v.y; }
        }
    }
    a0.x += a1.x; a0.y += a1.y;
    *(float2*)(g_agg + w * DD + 2 * lane) = a0;
}

// h_new = relu( (dis*agg) @ W^T ); acc += h_new; h' = dis*h_new; (last: out = acc/4)
__global__ void __launch_bounds__(256) k_gemm(const float* __restrict__ W,
                                              float* __restrict__ out, int last) {
    __shared__ float Ws[64 * 64];   // Ws[k*64 + col] = W[col*64 + k]
    __shared__ float As[32 * 64];   // As[r*64 + k] = dis[n] * agg[n*64 + k]

    int t = threadIdx.x;
    int row0 = blockIdx.x * 32;

    for (int i = t; i < 4096; i += 256) {
        int col = i >> 6, k = i & 63;
        Ws[k * 64 + col] = W[i];
    }
    for (int i = t; i < 2048; i += 256) {
        int r = i >> 6;
        int n = row0 + r;
        float v = 0.f;
        if (n < NN) v = g_dis[n] * g_agg[n * 64 + (i & 63)];
        As[i] = v;
    }
    __syncthreads();

    int r  = t >> 3;           // 0..31
    int c0 = (t & 7) * 8;      // 0,8,..,56
    float sum[8] = {0.f, 0.f, 0.f, 0.f, 0.f, 0.f, 0.f, 0.f};

    #pragma unroll
    for (int k = 0; k < 64; k++) {
        float a = As[r * 64 + k];
        float4 w0 = *(const float4*)&Ws[k * 64 + c0];
        float4 w1 = *(const float4*)&Ws[k * 64 + c0 + 4];
        sum[0] += a * w0.x; sum[1] += a * w0.y; sum[2] += a * w0.z; sum[3] += a * w0.w;
        sum[4] += a * w1.x; sum[5] += a * w1.y; sum[6] += a * w1.z; sum[7] += a * w1.w;
    }

    int n = row0 + r;
    if (n < NN) {
        float dn = g_dis[n];
        #pragma unroll
        for (int j = 0; j < 8; j++) {
            float v = fmaxf(sum[j], 0.f);
            int idx = n * 64 + c0 + j;
            float na = g_acc[idx] + v;
            g_acc[idx] = na;
            g_h[idx]   = dn * v;
            if (last) out[idx] = na * 0.25f;
        }
    }
}

// ---------------- launch --------------------------------------------------

extern "C" void kernel_launch(void* const* d_in, const int* in_sizes, int n_in,
                              void* d_out, int out_size) {
    const float* ue = (const float*)d_in[0];   // [NU, 64]
    const float* ie = (const float*)d_in[1];   // [NI, 64]
    const float* W  = (const float*)d_in[2];   // [3, 64, 64]
    const int*   ui = (const int*)d_in[3];     // [E]
    const int*   ii = (const int*)d_in[4];     // [E]
    float* out = (float*)d_out;                // [NN, 64]

    int E = in_sizes[3];
    if (E > EMAX) E = EMAX;

    k_zero_deg<<<(NN + 255) / 256, 256>>>();
    k_hist<<<(E + 255) / 256, 256>>>(ui, ii, E);
    k_scan<<<1, 1024>>>();
    k_scatter<<<(E + 255) / 256, 256>>>(ui, ii, E);
    k_init<<<(NN * DD + 255) / 256, 256>>>(ue, ie);

    for (int l = 0; l < LAYERS; l++) {
        k_spmm<<<NN / 8, 256>>>();                               // 150000 warps
        k_gemm<<<(NN + 31) / 32, 256>>>(W + l * 64 * 64, out, l == LAYERS - 1);
    }
}

// round 3
// speedup vs baseline: 1.2220x; 1.2220x over previous
#include <cuda_runtime.h>
#include <cuda_bf16.h>

#define NU     100000
#define NI     50000
#define NN     150000          // NU + NI
#define DD     64
#define EMAX   3000000
#define LAYERS 3
#define NB     ((NN + 255) / 256)   // 586 scan blocks

// ---------------- static device scratch (no allocations allowed) ----------
__device__ int   g_deg[NN];
__device__ int   g_rowptr[NN + 1];
__device__ int   g_cursor[NN];
__device__ int   g_bsum[NB];
__device__ int   g_boff[NB];
__device__ int   g_colidx[2 * EMAX];       // 24 MB
__device__ float g_dis[NN];
__device__ float g_h[2 * NN * DD];         // double-buffered h' = dis * h (76.8 MB)

// ---------------- CSR build ----------------------------------------------

__global__ void k_zero_deg() {
    int i = blockIdx.x * blockDim.x + threadIdx.x;
    if (i < NN) g_deg[i] = 0;
}

__global__ void k_hist(const int* __restrict__ ui, const int* __restrict__ ii, int E) {
    int e = blockIdx.x * blockDim.x + threadIdx.x;
    if (e < E) {
        atomicAdd(&g_deg[ui[e]], 1);
        atomicAdd(&g_deg[NU + ii[e]], 1);
    }
}

// 1) per-block (256-elem) sums, coalesced
__global__ void __launch_bounds__(256) k_sum() {
    __shared__ int wsum[8];
    int t = threadIdx.x, b = blockIdx.x;
    int i = b * 256 + t;
    int v = (i < NN) ? g_deg[i] : 0;
    #pragma unroll
    for (int o = 16; o > 0; o >>= 1) v += __shfl_down_sync(0xffffffffu, v, o);
    if ((t & 31) == 0) wsum[t >> 5] = v;
    __syncthreads();
    if (t == 0) {
        int s = 0;
        #pragma unroll
        for (int k = 0; k < 8; k++) s += wsum[k];
        g_bsum[b] = s;
    }
}

// 2) scan 586 block sums with one block
__global__ void __launch_bounds__(1024) k_scanb() {
    __shared__ int s[1024];
    int t = threadIdx.x;
    int v = (t < NB) ? g_bsum[t] : 0;
    s[t] = v;
    __syncthreads();
    for (int off = 1; off < 1024; off <<= 1) {
        int x = (t >= off) ? s[t - off] : 0;
        __syncthreads();
        s[t] += x;
        __syncthreads();
    }
    if (t < NB) g_boff[t] = s[t] - v;   // exclusive
}

// 3) block-local exclusive scan + write rowptr/cursor/dis, coalesced
__global__ void __launch_bounds__(256) k_scan3() {
    __shared__ int wsum[8];
    int t = threadIdx.x, b = blockIdx.x;
    int lane = t & 31, wid = t >> 5;
    int i = b * 256 + t;
    int d = (i < NN) ? g_deg[i] : 0;

    int inc = d;
    #pragma unroll
    for (int o = 1; o < 32; o <<= 1) {
        int x = __shfl_up_sync(0xffffffffu, inc, o);
        if (lane >= o) inc += x;
    }
    if (lane == 31) wsum[wid] = inc;
    __syncthreads();
    if (t == 0) {
        int run = 0;
        #pragma unroll
        for (int k = 0; k < 8; k++) { int v = wsum[k]; wsum[k] = run; run += v; }
    }
    __syncthreads();
    int off = g_boff[b] + wsum[wid] + inc - d;   // exclusive prefix
    if (i < NN) {
        g_rowptr[i] = off;
        g_cursor[i] = off;
        g_dis[i]    = rsqrtf((float)d + 1e-10f);
        if (i == NN - 1) g_rowptr[NN] = off + d;
    }
}

__global__ void k_scatter(const int* __restrict__ ui, const int* __restrict__ ii, int E) {
    int e = blockIdx.x * blockDim.x + threadIdx.x;
    if (e < E) {
        int u  = ui[e];
        int it = NU + ii[e];
        int p1 = atomicAdd(&g_cursor[u], 1);
        g_colidx[p1] = it;
        int p2 = atomicAdd(&g_cursor[it], 1);
        g_colidx[p2] = u;
    }
}

// out = x (accumulator lives in d_out) ; h'[buf 0] = dis * x
__global__ void k_init(const float* __restrict__ ue, const float* __restrict__ ie,
                       float* __restrict__ out) {
    int i = blockIdx.x * blockDim.x + threadIdx.x;
    if (i < NN * DD) {
        int n = i >> 6;
        float x = (n < NU) ? ue[i] : ie[i - NU * DD];
        out[i] = x;
        g_h[i] = g_dis[n] * x;
    }
}

// ---------------- fused layer: SpMM gather -> 64x64 GEMM -> epilogue ------
// Reads h' from buffer `parity`, writes next h' to buffer `parity^1`.
// No same-launch buffer is both read and written -> race-free.
__global__ void __launch_bounds__(256) k_layer(const float* __restrict__ W,
                                               float* __restrict__ out,
                                               int parity, int last) {
    __shared__ float Ws[64 * 64];   // Ws[k*64 + col] = W[col*64 + k]
    __shared__ float As[32 * 64];

    const float* __restrict__ hsrc = g_h + (size_t)parity * NN * DD;
    float* __restrict__       hdst = g_h + (size_t)(parity ^ 1) * NN * DD;

    int t = threadIdx.x;
    int row0 = blockIdx.x * 32;
    int w = t >> 5, lane = t & 31;

    for (int i = t; i < 4096; i += 256) {
        int col = i >> 6, k = i & 63;
        Ws[k * 64 + col] = W[i];
    }

    // gather phase: warp w handles rows w*4 .. w*4+3
    #pragma unroll
    for (int rr = 0; rr < 4; rr++) {
        int r = w * 4 + rr;
        int n = row0 + r;
        float2 a0 = make_float2(0.f, 0.f);
        float2 a1 = make_float2(0.f, 0.f);
        if (n < NN) {
            int s = g_rowptr[n];
            int e = g_rowptr[n + 1];
            for (int base = s; base < e; base += 32) {
                int c = 0;
                int cnt = e - base; if (cnt > 32) cnt = 32;
                if (lane < cnt) c = g_colidx[base + lane];
                #pragma unroll 4
                for (int j = 0; j < cnt; j++) {
                    int cc = __shfl_sync(0xffffffffu, c, j);
                    float2 v = *(const float2*)(hsrc + cc * DD + 2 * lane);
                    if (j & 1) { a1.x += v.x; a1.y += v.y; }
                    else       { a0.x += v.x; a0.y += v.y; }
                }
            }
            float dn = g_dis[n];
            a0.x = (a0.x + a1.x) * dn;
            a0.y = (a0.y + a1.y) * dn;
        }
        *(float2*)&As[r * 64 + 2 * lane] = a0;
    }
    __syncthreads();

    // GEMM phase: thread -> (row r = t>>3, cols c0..c0+7)
    int r  = t >> 3;
    int c0 = (t & 7) * 8;
    float sum[8] = {0.f, 0.f, 0.f, 0.f, 0.f, 0.f, 0.f, 0.f};

    #pragma unroll
    for (int k = 0; k < 64; k++) {
        float a = As[r * 64 + k];
        float4 w0 = *(const float4*)&Ws[k * 64 + c0];
        float4 w1 = *(const float4*)&Ws[k * 64 + c0 + 4];
        sum[0] += a * w0.x; sum[1] += a * w0.y; sum[2] += a * w0.z; sum[3] += a * w0.w;
        sum[4] += a * w1.x; sum[5] += a * w1.y; sum[6] += a * w1.z; sum[7] += a * w1.w;
    }

    int n = row0 + r;
    if (n < NN) {
        float dn = g_dis[n];
        #pragma unroll
        for (int j = 0; j < 8; j++) {
            float v = fmaxf(sum[j], 0.f);
            int idx = n * 64 + c0 + j;
            float na = out[idx] + v;
            hdst[idx] = dn * v;
            out[idx]  = last ? na * 0.25f : na;
        }
    }
}

// ---------------- launch --------------------------------------------------

extern "C" void kernel_launch(void* const* d_in, const int* in_sizes, int n_in,
                              void* d_out, int out_size) {
    const float* ue = (const float*)d_in[0];   // [NU, 64]
    const float* ie = (const float*)d_in[1];   // [NI, 64]
    const float* W  = (const float*)d_in[2];   // [3, 64, 64]
    const int*   ui = (const int*)d_in[3];     // [E]
    const int*   ii = (const int*)d_in[4];     // [E]
    float* out = (float*)d_out;                // [NN, 64]

    int E = in_sizes[3];
    if (E > EMAX) E = EMAX;

    k_zero_deg<<<(NN + 255) / 256, 256>>>();
    k_hist<<<(E + 255) / 256, 256>>>(ui, ii, E);
    k_sum<<<NB, 256>>>();
    k_scanb<<<1, 1024>>>();
    k_scan3<<<NB, 256>>>();
    k_scatter<<<(E + 255) / 256, 256>>>(ui, ii, E);
    k_init<<<(NN * DD + 255) / 256, 256>>>(ue, ie, out);

    for (int l = 0; l < LAYERS; l++) {
        k_layer<<<(NN + 31) / 32, 256>>>(W + l * 64 * 64, out, l & 1, l == LAYERS - 1);
    }
}

// round 4
// speedup vs baseline: 1.2828x; 1.0497x over previous
#include <cuda_runtime.h>
#include <cuda_bf16.h>

#define NU     100000
#define NI     50000
#define NN     150000          // NU + NI
#define DD     64
#define EMAX   3000000
#define LAYERS 3
#define NB     ((NN + 255) / 256)   // 586 scan blocks

// ---------------- static device scratch (no allocations allowed) ----------
__device__ int   g_deg[NN];
__device__ int   g_rowptr[NN + 1];
__device__ int   g_cursor[NN];
__device__ int   g_bsum[NB];
__device__ int   g_boff[NB];
__device__ int   g_colidx[2 * EMAX];       // 24 MB
__device__ float g_dis[NN];
__device__ float g_h[2 * NN * DD];         // double-buffered h' = dis * h (76.8 MB)

// ---------------- CSR build ----------------------------------------------

__global__ void k_zero_deg() {
    int i = blockIdx.x * blockDim.x + threadIdx.x;
    if (i < NN) g_deg[i] = 0;
}

__global__ void k_hist(const int* __restrict__ ui, const int* __restrict__ ii, int E) {
    int e = blockIdx.x * blockDim.x + threadIdx.x;
    if (e < E) {
        atomicAdd(&g_deg[__ldcs(ui + e)], 1);
        atomicAdd(&g_deg[NU + __ldcs(ii + e)], 1);
    }
}

// 1) per-block (256-elem) sums, coalesced
__global__ void __launch_bounds__(256) k_sum() {
    __shared__ int wsum[8];
    int t = threadIdx.x, b = blockIdx.x;
    int i = b * 256 + t;
    int v = (i < NN) ? g_deg[i] : 0;
    #pragma unroll
    for (int o = 16; o > 0; o >>= 1) v += __shfl_down_sync(0xffffffffu, v, o);
    if ((t & 31) == 0) wsum[t >> 5] = v;
    __syncthreads();
    if (t == 0) {
        int s = 0;
        #pragma unroll
        for (int k = 0; k < 8; k++) s += wsum[k];
        g_bsum[b] = s;
    }
}

// 2) scan 586 block sums with one block
__global__ void __launch_bounds__(1024) k_scanb() {
    __shared__ int s[1024];
    int t = threadIdx.x;
    int v = (t < NB) ? g_bsum[t] : 0;
    s[t] = v;
    __syncthreads();
    for (int off = 1; off < 1024; off <<= 1) {
        int x = (t >= off) ? s[t - off] : 0;
        __syncthreads();
        s[t] += x;
        __syncthreads();
    }
    if (t < NB) g_boff[t] = s[t] - v;   // exclusive
}

// 3) block-local exclusive scan + write rowptr/cursor/dis, coalesced
__global__ void __launch_bounds__(256) k_scan3() {
    __shared__ int wsum[8];
    int t = threadIdx.x, b = blockIdx.x;
    int lane = t & 31, wid = t >> 5;
    int i = b * 256 + t;
    int d = (i < NN) ? g_deg[i] : 0;

    int inc = d;
    #pragma unroll
    for (int o = 1; o < 32; o <<= 1) {
        int x = __shfl_up_sync(0xffffffffu, inc, o);
        if (lane >= o) inc += x;
    }
    if (lane == 31) wsum[wid] = inc;
    __syncthreads();
    if (t == 0) {
        int run = 0;
        #pragma unroll
        for (int k = 0; k < 8; k++) { int v = wsum[k]; wsum[k] = run; run += v; }
    }
    __syncthreads();
    int off = g_boff[b] + wsum[wid] + inc - d;   // exclusive prefix
    if (i < NN) {
        g_rowptr[i] = off;
        g_cursor[i] = off;
        g_dis[i]    = rsqrtf((float)d + 1e-10f);
        if (i == NN - 1) g_rowptr[NN] = off + d;
    }
}

__global__ void k_scatter(const int* __restrict__ ui, const int* __restrict__ ii, int E) {
    int e = blockIdx.x * blockDim.x + threadIdx.x;
    if (e < E) {
        int u  = __ldcs(ui + e);
        int it = NU + __ldcs(ii + e);
        int p1 = atomicAdd(&g_cursor[u], 1);
        g_colidx[p1] = it;
        int p2 = atomicAdd(&g_cursor[it], 1);
        g_colidx[p2] = u;
    }
}

// out = x (accumulator lives in d_out) ; h'[buf 0] = dis * x
__global__ void k_init(const float* __restrict__ ue, const float* __restrict__ ie,
                       float* __restrict__ out) {
    int i = blockIdx.x * blockDim.x + threadIdx.x;
    if (i < NN * DD) {
        int n = i >> 6;
        float x = (n < NU) ? __ldcs(ue + i) : __ldcs(ie + i - NU * DD);
        __stcs(out + i, x);
        g_h[i] = g_dis[n] * x;   // default policy: wants to live in L2
    }
}

// ---------------- fused layer: SpMM gather -> 64x64 GEMM -> epilogue ------
// Reads h' from buffer `parity` (L2-persisting), writes next h' to buffer
// `parity^1` and `out` with streaming hints so they don't evict hsrc.
__global__ void __launch_bounds__(256) k_layer(const float* __restrict__ W,
                                               float* __restrict__ out,
                                               int parity, int last) {
    __shared__ float Ws[64 * 64];   // Ws[k*64 + col] = W[col*64 + k]
    __shared__ float As[32 * 64];

    const float* __restrict__ hsrc = g_h + (size_t)parity * NN * DD;
    float* __restrict__       hdst = g_h + (size_t)(parity ^ 1) * NN * DD;

    int t = threadIdx.x;
    int row0 = blockIdx.x * 32;
    int w = t >> 5, lane = t & 31;
    int half = lane >> 4;          // 0 or 1
    int hl   = lane & 15;          // 0..15

    for (int i = t; i < 4096; i += 256) {
        int col = i >> 6, k = i & 63;
        Ws[k * 64 + col] = W[i];
    }

    // gather phase: warp w handles rows w*4 .. w*4+3.
    // Half-warps process edges pairwise: half h takes edge j+h, loading the
    // full 256B row via 16 lanes x float4.
    #pragma unroll
    for (int rr = 0; rr < 4; rr++) {
        int r = w * 4 + rr;
        int n = row0 + r;
        float4 acc = make_float4(0.f, 0.f, 0.f, 0.f);
        if (n < NN) {
            int s = g_rowptr[n];
            int e = g_rowptr[n + 1];
            for (int base = s; base < e; base += 32) {
                int c = 0;
                int cnt = e - base; if (cnt > 32) cnt = 32;
                if (lane < cnt) c = __ldcs(g_colidx + base + lane);
                #pragma unroll 2
                for (int j = 0; j < cnt; j += 2) {
                    int cc = __shfl_sync(0xffffffffu, c, j + half);
                    if (j + half < cnt) {
                        float4 v = *(const float4*)(hsrc + cc * DD + 4 * hl);
                        acc.x += v.x; acc.y += v.y; acc.z += v.z; acc.w += v.w;
                    }
                }
            }
            // combine the two half-warp partial sums
            acc.x += __shfl_xor_sync(0xffffffffu, acc.x, 16);
            acc.y += __shfl_xor_sync(0xffffffffu, acc.y, 16);
            acc.z += __shfl_xor_sync(0xffffffffu, acc.z, 16);
            acc.w += __shfl_xor_sync(0xffffffffu, acc.w, 16);
            float dn = g_dis[n];
            acc.x *= dn; acc.y *= dn; acc.z *= dn; acc.w *= dn;
        }
        if (half == 0) *(float4*)&As[r * 64 + 4 * hl] = acc;
    }
    __syncthreads();

    // GEMM phase: thread -> (row r = t>>3, cols c0..c0+7)
    int r  = t >> 3;
    int c0 = (t & 7) * 8;
    float sum[8] = {0.f, 0.f, 0.f, 0.f, 0.f, 0.f, 0.f, 0.f};

    #pragma unroll
    for (int k = 0; k < 64; k++) {
        float a = As[r * 64 + k];
        float4 w0 = *(const float4*)&Ws[k * 64 + c0];
        float4 w1 = *(const float4*)&Ws[k * 64 + c0 + 4];
        sum[0] += a * w0.x; sum[1] += a * w0.y; sum[2] += a * w0.z; sum[3] += a * w0.w;
        sum[4] += a * w1.x; sum[5] += a * w1.y; sum[6] += a * w1.z; sum[7] += a * w1.w;
    }

    int n = row0 + r;
    if (n < NN) {
        float dn = g_dis[n];
        #pragma unroll
        for (int j = 0; j < 8; j++) {
            float v = fmaxf(sum[j], 0.f);
            int idx = n * 64 + c0 + j;
            float na = __ldcs(out + idx) + v;
            __stcs(hdst + idx, dn * v);
            __stcs(out + idx, last ? na * 0.25f : na);
        }
    }
}

// ---------------- launch --------------------------------------------------

extern "C" void kernel_launch(void* const* d_in, const int* in_sizes, int n_in,
                              void* d_out, int out_size) {
    const float* ue = (const float*)d_in[0];   // [NU, 64]
    const float* ie = (const float*)d_in[1];   // [NI, 64]
    const float* W  = (const float*)d_in[2];   // [3, 64, 64]
    const int*   ui = (const int*)d_in[3];     // [E]
    const int*   ii = (const int*)d_in[4];     // [E]
    float* out = (float*)d_out;                // [NN, 64]

    int E = in_sizes[3];
    if (E > EMAX) E = EMAX;

    k_zero_deg<<<(NN + 255) / 256, 256>>>();
    k_hist<<<(E + 255) / 256, 256>>>(ui, ii, E);
    k_sum<<<NB, 256>>>();
    k_scanb<<<1, 1024>>>();
    k_scan3<<<NB, 256>>>();
    k_scatter<<<(E + 255) / 256, 256>>>(ui, ii, E);
    k_init<<<(NN * DD + 255) / 256, 256>>>(ue, ie, out);

    for (int l = 0; l < LAYERS; l++) {
        k_layer<<<(NN + 31) / 32, 256>>>(W + l * 64 * 64, out, l & 1, l == LAYERS - 1);
    }
}

// round 5
// speedup vs baseline: 1.7360x; 1.3533x over previous
#include <cuda_runtime.h>
#include <cuda_fp16.h>
#include <cuda_bf16.h>

#define NU     100000
#define NI     50000
#define NN     150000          // NU + NI
#define DD     64
#define EMAX   3000000
#define LAYERS 3
#define NB     ((NN + 255) / 256)   // 586 scan blocks

// ---------------- static device scratch (no allocations allowed) ----------
__device__ int   g_deg[NN];
__device__ int   g_rowptr[NN + 1];
__device__ int   g_cursor[NN];
__device__ int   g_bsum[NB];
__device__ int   g_boff[NB];
__device__ int   g_colidx[2 * EMAX];                    // 24 MB, reused 3x -> default policy
__device__ float g_dis[NN];
__device__ __align__(16) __half g_h[2 * NN * DD];       // double-buffered fp16 h' (38.4 MB total)

// ---------------- CSR build ----------------------------------------------

__global__ void k_zero_deg() {
    int i = blockIdx.x * blockDim.x + threadIdx.x;
    if (i < NN) g_deg[i] = 0;
}

__global__ void k_hist(const int* __restrict__ ui, const int* __restrict__ ii, int E) {
    int e = blockIdx.x * blockDim.x + threadIdx.x;
    if (e < E) {
        atomicAdd(&g_deg[__ldcs(ui + e)], 1);
        atomicAdd(&g_deg[NU + __ldcs(ii + e)], 1);
    }
}

__global__ void __launch_bounds__(256) k_sum() {
    __shared__ int wsum[8];
    int t = threadIdx.x, b = blockIdx.x;
    int i = b * 256 + t;
    int v = (i < NN) ? g_deg[i] : 0;
    #pragma unroll
    for (int o = 16; o > 0; o >>= 1) v += __shfl_down_sync(0xffffffffu, v, o);
    if ((t & 31) == 0) wsum[t >> 5] = v;
    __syncthreads();
    if (t == 0) {
        int s = 0;
        #pragma unroll
        for (int k = 0; k < 8; k++) s += wsum[k];
        g_bsum[b] = s;
    }
}

__global__ void __launch_bounds__(1024) k_scanb() {
    __shared__ int s[1024];
    int t = threadIdx.x;
    int v = (t < NB) ? g_bsum[t] : 0;
    s[t] = v;
    __syncthreads();
    for (int off = 1; off < 1024; off <<= 1) {
        int x = (t >= off) ? s[t - off] : 0;
        __syncthreads();
        s[t] += x;
        __syncthreads();
    }
    if (t < NB) g_boff[t] = s[t] - v;   // exclusive
}

__global__ void __launch_bounds__(256) k_scan3() {
    __shared__ int wsum[8];
    int t = threadIdx.x, b = blockIdx.x;
    int lane = t & 31, wid = t >> 5;
    int i = b * 256 + t;
    int d = (i < NN) ? g_deg[i] : 0;

    int inc = d;
    #pragma unroll
    for (int o = 1; o < 32; o <<= 1) {
        int x = __shfl_up_sync(0xffffffffu, inc, o);
        if (lane >= o) inc += x;
    }
    if (lane == 31) wsum[wid] = inc;
    __syncthreads();
    if (t == 0) {
        int run = 0;
        #pragma unroll
        for (int k = 0; k < 8; k++) { int v = wsum[k]; wsum[k] = run; run += v; }
    }
    __syncthreads();
    int off = g_boff[b] + wsum[wid] + inc - d;
    if (i < NN) {
        g_rowptr[i] = off;
        g_cursor[i] = off;
        g_dis[i]    = rsqrtf((float)d + 1e-10f);
        if (i == NN - 1) g_rowptr[NN] = off + d;
    }
}

__global__ void k_scatter(const int* __restrict__ ui, const int* __restrict__ ii, int E) {
    int e = blockIdx.x * blockDim.x + threadIdx.x;
    if (e < E) {
        int u  = __ldcs(ui + e);
        int it = NU + __ldcs(ii + e);
        int p1 = atomicAdd(&g_cursor[u], 1);
        g_colidx[p1] = it;
        int p2 = atomicAdd(&g_cursor[it], 1);
        g_colidx[p2] = u;
    }
}

// out = x ; h'[buf 0] = fp16(dis * x).  2 elems / thread (half2 stores).
__global__ void k_init(const float* __restrict__ ue, const float* __restrict__ ie,
                       float* __restrict__ out) {
    int p = blockIdx.x * blockDim.x + threadIdx.x;   // pair index
    if (p < NN * DD / 2) {
        int i = p * 2;
        int n = i >> 6;
        float2 x = (n < NU) ? *(const float2*)(ue + i)
                            : *(const float2*)(ie + i - NU * DD);
        __stcs((float2*)(out + i), x);
        float dn = g_dis[n];
        *(__half2*)(g_h + i) = __floats2half2_rn(dn * x.x, dn * x.y);
    }
}

// ---------------- fused layer: gather(SpMM) -> 64x64 GEMM -> epilogue -----
// Block covers 128 rows. Warp w gathers rows w*16..w*16+15 into As (stride 68).
// GEMM: thread -> rows rb+{0,32,64,96}, cols g*8..g*8+7; Ws deswizzled so each
// LDS.128 is bank-conflict-free.  h' fp16 double-buffered (race-free).
__global__ void __launch_bounds__(256) k_layer(const float* __restrict__ W,
                                               float* __restrict__ out,
                                               int parity, int last) {
    __shared__ float Ws[64 * 64];    // Ws[k*64 + hh*32 + g*4 + pos] = W[col*64+k]
    __shared__ float As[128 * 68];

    const __half* __restrict__ hsrc = g_h + (size_t)parity * NN * DD;
    __half* __restrict__       hdst = g_h + (size_t)(parity ^ 1) * NN * DD;

    int t = threadIdx.x;
    int row0 = blockIdx.x * 128;
    int w = t >> 5, lane = t & 31;
    int half = lane >> 4;          // 0 or 1
    int hl   = lane & 15;          // 0..15

    // W[col*64 + k] -> deswizzled Ws
    for (int i = t; i < 4096; i += 256) {
        int col = i >> 6, k = i & 63;
        int g = col >> 3, hh = (col >> 2) & 1, pos = col & 3;
        Ws[k * 64 + hh * 32 + g * 4 + pos] = W[i];
    }

    // gather: warp w -> rows w*16 .. w*16+15; half-warps take edges pairwise,
    // each half loads a full 128B fp16 row with 16 lanes x 8B.
    for (int rr = 0; rr < 16; rr++) {
        int r = w * 16 + rr;
        int n = row0 + r;
        float4 acc = make_float4(0.f, 0.f, 0.f, 0.f);
        if (n < NN) {
            int s = g_rowptr[n];
            int e = g_rowptr[n + 1];
            for (int base = s; base < e; base += 32) {
                int c = 0;
                int cnt = e - base; if (cnt > 32) cnt = 32;
                if (lane < cnt) c = g_colidx[base + lane];
                #pragma unroll 2
                for (int j = 0; j < cnt; j += 2) {
                    int cc = __shfl_sync(0xffffffffu, c, j + half);
                    if (j + half < cnt) {
                        uint2 raw = *(const uint2*)(hsrc + cc * DD + 4 * hl);
                        float2 v0 = __half22float2(*(__half2*)&raw.x);
                        float2 v1 = __half22float2(*(__half2*)&raw.y);
                        acc.x += v0.x; acc.y += v0.y; acc.z += v1.x; acc.w += v1.y;
                    }
                }
            }
            acc.x += __shfl_xor_sync(0xffffffffu, acc.x, 16);
            acc.y += __shfl_xor_sync(0xffffffffu, acc.y, 16);
            acc.z += __shfl_xor_sync(0xffffffffu, acc.z, 16);
            acc.w += __shfl_xor_sync(0xffffffffu, acc.w, 16);
            float dn = g_dis[n];
            acc.x *= dn; acc.y *= dn; acc.z *= dn; acc.w *= dn;
        }
        if (half == 0) *(float4*)&As[r * 68 + 4 * hl] = acc;
    }
    __syncthreads();

    // GEMM: thread -> rows rb, rb+32, rb+64, rb+96; cols g*8..g*8+7
    int rb = t >> 3;     // 0..31
    int g  = t & 7;      // 0..7
    float sum[4][8];
    #pragma unroll
    for (int m = 0; m < 4; m++)
        #pragma unroll
        for (int j = 0; j < 8; j++) sum[m][j] = 0.f;

    #pragma unroll 4
    for (int k = 0; k < 64; k++) {
        float4 w0 = *(const float4*)&Ws[k * 64 + g * 4];        // cols g*8..g*8+3
        float4 w1 = *(const float4*)&Ws[k * 64 + 32 + g * 4];   // cols g*8+4..g*8+7
        float a0 = As[(rb      ) * 68 + k];
        float a1 = As[(rb +  32) * 68 + k];
        float a2 = As[(rb +  64) * 68 + k];
        float a3 = As[(rb +  96) * 68 + k];
        sum[0][0] += a0 * w0.x; sum[0][1] += a0 * w0.y; sum[0][2] += a0 * w0.z; sum[0][3] += a0 * w0.w;
        sum[0][4] += a0 * w1.x; sum[0][5] += a0 * w1.y; sum[0][6] += a0 * w1.z; sum[0][7] += a0 * w1.w;
        sum[1][0] += a1 * w0.x; sum[1][1] += a1 * w0.y; sum[1][2] += a1 * w0.z; sum[1][3] += a1 * w0.w;
        sum[1][4] += a1 * w1.x; sum[1][5] += a1 * w1.y; sum[1][6] += a1 * w1.z; sum[1][7] += a1 * w1.w;
        sum[2][0] += a2 * w0.x; sum[2][1] += a2 * w0.y; sum[2][2] += a2 * w0.z; sum[2][3] += a2 * w0.w;
        sum[2][4] += a2 * w1.x; sum[2][5] += a2 * w1.y; sum[2][6] += a2 * w1.z; sum[2][7] += a2 * w1.w;
        sum[3][0] += a3 * w0.x; sum[3][1] += a3 * w0.y; sum[3][2] += a3 * w0.z; sum[3][3] += a3 * w0.w;
        sum[3][4] += a3 * w1.x; sum[3][5] += a3 * w1.y; sum[3][6] += a3 * w1.z; sum[3][7] += a3 * w1.w;
    }

    int c0 = g * 8;
    #pragma unroll
    for (int m = 0; m < 4; m++) {
        int n = row0 + rb + 32 * m;
        if (n < NN) {
            float dn = g_dis[n];
            int idx = n * 64 + c0;
            float4 o0 = __ldcs((const float4*)(out + idx));
            float4 o1 = __ldcs((const float4*)(out + idx + 4));
            float v[8];
            #pragma unroll
            for (int j = 0; j < 8; j++) v[j] = fmaxf(sum[m][j], 0.f);
            o0.x += v[0]; o0.y += v[1]; o0.z += v[2]; o0.w += v[3];
            o1.x += v[4]; o1.y += v[5]; o1.z += v[6]; o1.w += v[7];
            if (last) {
                o0.x *= 0.25f; o0.y *= 0.25f; o0.z *= 0.25f; o0.w *= 0.25f;
                o1.x *= 0.25f; o1.y *= 0.25f; o1.z *= 0.25f; o1.w *= 0.25f;
            }
            __stcs((float4*)(out + idx), o0);
            __stcs((float4*)(out + idx + 4), o1);
            // pack 8 halves of dn*v into one 16B store
            __half2 hpack[4];
            #pragma unroll
            for (int j = 0; j < 4; j++)
                hpack[j] = __floats2half2_rn(dn * v[2 * j], dn * v[2 * j + 1]);
            __stcs((uint4*)(hdst + idx), *(uint4*)hpack);
        }
    }
}

// ---------------- launch --------------------------------------------------

extern "C" void kernel_launch(void* const* d_in, const int* in_sizes, int n_in,
                              void* d_out, int out_size) {
    const float* ue = (const float*)d_in[0];   // [NU, 64]
    const float* ie = (const float*)d_in[1];   // [NI, 64]
    const float* W  = (const float*)d_in[2];   // [3, 64, 64]
    const int*   ui = (const int*)d_in[3];     // [E]
    const int*   ii = (const int*)d_in[4];     // [E]
    float* out = (float*)d_out;                // [NN, 64]

    int E = in_sizes[3];
    if (E > EMAX) E = EMAX;

    k_zero_deg<<<(NN + 255) / 256, 256>>>();
    k_hist<<<(E + 255) / 256, 256>>>(ui, ii, E);
    k_sum<<<NB, 256>>>();
    k_scanb<<<1, 1024>>>();
    k_scan3<<<NB, 256>>>();
    k_scatter<<<(E + 255) / 256, 256>>>(ui, ii, E);
    k_init<<<(NN * DD / 2 + 255) / 256, 256>>>(ue, ie, out);

    for (int l = 0; l < LAYERS; l++) {
        k_layer<<<(NN + 127) / 128, 256>>>(W + l * 64 * 64, out, l & 1, l == LAYERS - 1);
    }
}

// round 6
// speedup vs baseline: 2.1077x; 1.2141x over previous
#include <cuda_runtime.h>
#include <cuda_fp16.h>
#include <cuda_bf16.h>

#define NU     100000
#define NI     50000
#define NN     150000          // NU + NI
#define DD     64
#define EMAX   3000000
#define LAYERS 3
#define NB     ((NN + 255) / 256)   // 586 scan blocks

// ---------------- static device scratch (no allocations allowed) ----------
__device__ int   g_deg[NN];              // zero-init; re-zeroed by k_scan1 every run
__device__ int   g_rowptr[NN + 1];
__device__ int   g_cursor[NN];
__device__ int   g_bsum[NB];
__device__ int   g_flag[NB];             // zero-init; reset by k_scatterinit every run
__device__ int   g_colidx[2 * EMAX];     // 24 MB
__device__ float g_dis[NN];
__device__ __align__(16) __half g_h[2 * NN * DD];   // double-buffered fp16 h'

// ---------------- CSR build ----------------------------------------------

__global__ void k_hist(const int* __restrict__ ui, const int* __restrict__ ii, int E) {
    int e = blockIdx.x * blockDim.x + threadIdx.x;
    if (e < E) {
        atomicAdd(&g_deg[__ldcs(ui + e)], 1);
        atomicAdd(&g_deg[NU + __ldcs(ii + e)], 1);
    }
}

// single-launch scan: local scan + publish aggregate + sum predecessor
// aggregates (decoupled lookback, no chaining). Also zeroes g_deg for the
// next graph replay.
__global__ void __launch_bounds__(256) k_scan1() {
    __shared__ int wsum[8];
    __shared__ int sboff;
    int t = threadIdx.x, b = blockIdx.x;
    int lane = t & 31, wid = t >> 5;
    int i = b * 256 + t;

    int d = 0;
    if (i < NN) { d = g_deg[i]; g_deg[i] = 0; }

    // warp inclusive scan
    int inc = d;
    #pragma unroll
    for (int o = 1; o < 32; o <<= 1) {
        int x = __shfl_up_sync(0xffffffffu, inc, o);
        if (lane >= o) inc += x;
    }
    if (lane == 31) wsum[wid] = inc;
    if (t == 0) sboff = 0;
    __syncthreads();
    if (t == 0) {
        int run = 0;
        #pragma unroll
        for (int k = 0; k < 8; k++) { int v = wsum[k]; wsum[k] = run; run += v; }
        g_bsum[b] = run;                 // block aggregate
        __threadfence();
        atomicExch(&g_flag[b], 1);       // publish
    }
    __syncthreads();

    // lookback: sum aggregates of all predecessor blocks
    int acc = 0;
    for (int j = t; j < b; j += 256) {
        while (((volatile int*)g_flag)[j] == 0) { }
        __threadfence();
        acc += ((volatile int*)g_bsum)[j];
    }
    #pragma unroll
    for (int o = 16; o > 0; o >>= 1) acc += __shfl_down_sync(0xffffffffu, acc, o);
    if (lane == 0 && acc != 0) atomicAdd(&sboff, acc);
    __syncthreads();

    int off = sboff + wsum[wid] + inc - d;   // exclusive global prefix
    if (i < NN) {
        g_rowptr[i] = off;
        g_cursor[i] = off;
        g_dis[i]    = rsqrtf((float)d + 1e-10f);
        if (i == NN - 1) g_rowptr[NN] = off + d;
    }
}

// fused scatter (blocks [0, nScatter)) + init (blocks [nScatter, ...)).
// Also resets g_flag for the next graph replay.
__global__ void __launch_bounds__(256) k_scatterinit(
        const int* __restrict__ ui, const int* __restrict__ ii, int E,
        const float* __restrict__ ue, const float* __restrict__ ie,
        float* __restrict__ out, int nScatter) {
    int b = blockIdx.x, t = threadIdx.x;
    if (b < nScatter) {
        int e = b * 256 + t;
        if (e < NB) g_flag[e] = 0;       // safe: k_scan1 fully done
        if (e < E) {
            int u  = __ldcs(ui + e);
            int it = NU + __ldcs(ii + e);
            int p1 = atomicAdd(&g_cursor[u], 1);
            g_colidx[p1] = it;
            int p2 = atomicAdd(&g_cursor[it], 1);
            g_colidx[p2] = u;
        }
    } else {
        int p = (b - nScatter) * 256 + t;    // pair index
        if (p < NN * DD / 2) {
            int i = p * 2;
            int n = i >> 6;
            float2 x = (n < NU) ? *(const float2*)(ue + i)
                                : *(const float2*)(ie + i - NU * DD);
            __stcs((float2*)(out + i), x);
            float dn = g_dis[n];
            *(__half2*)(g_h + i) = __floats2half2_rn(dn * x.x, dn * x.y);
        }
    }
}

// ---------------- fused layer: gather(SpMM) -> 64x64 GEMM -> epilogue -----
__global__ void __launch_bounds__(256) k_layer(const float* __restrict__ W,
                                               float* __restrict__ out,
                                               int parity, int last) {
    __shared__ float Ws[64 * 64];    // deswizzled: Ws[k*64 + hh*32 + g*4 + pos]
    __shared__ float As[128 * 68];

    const __half* __restrict__ hsrc = g_h + (size_t)parity * NN * DD;
    __half* __restrict__       hdst = g_h + (size_t)(parity ^ 1) * NN * DD;

    int t = threadIdx.x;
    int row0 = blockIdx.x * 128;
    int w = t >> 5, lane = t & 31;
    int half = lane >> 4;          // 0 or 1
    int hl   = lane & 15;          // 0..15

    for (int i = t; i < 4096; i += 256) {
        int col = i >> 6, k = i & 63;
        int g = col >> 3, hh = (col >> 2) & 1, pos = col & 3;
        Ws[k * 64 + hh * 32 + g * 4 + pos] = W[i];
    }

    // gather: warp w -> rows w*16 .. w*16+15; half-warps take edges pairwise,
    // each half loads a full 128B fp16 row with 16 lanes x 8B. unroll 4 -> 4
    // independent LDGs in flight per half-warp.
    for (int rr = 0; rr < 16; rr++) {
        int r = w * 16 + rr;
        int n = row0 + r;
        float4 acc = make_float4(0.f, 0.f, 0.f, 0.f);
        if (n < NN) {
            int s = g_rowptr[n];
            int e = g_rowptr[n + 1];
            for (int base = s; base < e; base += 32) {
                int c = 0;
                int cnt = e - base; if (cnt > 32) cnt = 32;
                if (lane < cnt) c = g_colidx[base + lane];
                #pragma unroll 4
                for (int j = 0; j < cnt; j += 2) {
                    int cc = __shfl_sync(0xffffffffu, c, j + half);
                    if (j + half < cnt) {
                        uint2 raw = *(const uint2*)(hsrc + cc * DD + 4 * hl);
                        float2 v0 = __half22float2(*(__half2*)&raw.x);
                        float2 v1 = __half22float2(*(__half2*)&raw.y);
                        acc.x += v0.x; acc.y += v0.y; acc.z += v1.x; acc.w += v1.y;
                    }
                }
            }
            acc.x += __shfl_xor_sync(0xffffffffu, acc.x, 16);
            acc.y += __shfl_xor_sync(0xffffffffu, acc.y, 16);
            acc.z += __shfl_xor_sync(0xffffffffu, acc.z, 16);
            acc.w += __shfl_xor_sync(0xffffffffu, acc.w, 16);
            float dn = g_dis[n];
            acc.x *= dn; acc.y *= dn; acc.z *= dn; acc.w *= dn;
        }
        if (half == 0) *(float4*)&As[r * 68 + 4 * hl] = acc;
    }
    __syncthreads();

    // GEMM: thread -> rows rb+{0,32,64,96}, cols g*8..g*8+7
    int rb = t >> 3;     // 0..31
    int g  = t & 7;      // 0..7
    float sum[4][8];
    #pragma unroll
    for (int m = 0; m < 4; m++)
        #pragma unroll
        for (int j = 0; j < 8; j++) sum[m][j] = 0.f;

    #pragma unroll 4
    for (int k = 0; k < 64; k++) {
        float4 w0 = *(const float4*)&Ws[k * 64 + g * 4];
        float4 w1 = *(const float4*)&Ws[k * 64 + 32 + g * 4];
        float a0 = As[(rb      ) * 68 + k];
        float a1 = As[(rb +  32) * 68 + k];
        float a2 = As[(rb +  64) * 68 + k];
        float a3 = As[(rb +  96) * 68 + k];
        sum[0][0] += a0 * w0.x; sum[0][1] += a0 * w0.y; sum[0][2] += a0 * w0.z; sum[0][3] += a0 * w0.w;
        sum[0][4] += a0 * w1.x; sum[0][5] += a0 * w1.y; sum[0][6] += a0 * w1.z; sum[0][7] += a0 * w1.w;
        sum[1][0] += a1 * w0.x; sum[1][1] += a1 * w0.y; sum[1][2] += a1 * w0.z; sum[1][3] += a1 * w0.w;
        sum[1][4] += a1 * w1.x; sum[1][5] += a1 * w1.y; sum[1][6] += a1 * w1.z; sum[1][7] += a1 * w1.w;
        sum[2][0] += a2 * w0.x; sum[2][1] += a2 * w0.y; sum[2][2] += a2 * w0.z; sum[2][3] += a2 * w0.w;
        sum[2][4] += a2 * w1.x; sum[2][5] += a2 * w1.y; sum[2][6] += a2 * w1.z; sum[2][7] += a2 * w1.w;
        sum[3][0] += a3 * w0.x; sum[3][1] += a3 * w0.y; sum[3][2] += a3 * w0.z; sum[3][3] += a3 * w0.w;
        sum[3][4] += a3 * w1.x; sum[3][5] += a3 * w1.y; sum[3][6] += a3 * w1.z; sum[3][7] += a3 * w1.w;
    }

    int c0 = g * 8;
    #pragma unroll
    for (int m = 0; m < 4; m++) {
        int n = row0 + rb + 32 * m;
        if (n < NN) {
            float dn = g_dis[n];
            int idx = n * 64 + c0;
            float4 o0 = __ldcs((const float4*)(out + idx));
            float4 o1 = __ldcs((const float4*)(out + idx + 4));
            float v[8];
            #pragma unroll
            for (int j = 0; j < 8; j++) v[j] = fmaxf(sum[m][j], 0.f);
            o0.x += v[0]; o0.y += v[1]; o0.z += v[2]; o0.w += v[3];
            o1.x += v[4]; o1.y += v[5]; o1.z += v[6]; o1.w += v[7];
            if (last) {
                o0.x *= 0.25f; o0.y *= 0.25f; o0.z *= 0.25f; o0.w *= 0.25f;
                o1.x *= 0.25f; o1.y *= 0.25f; o1.z *= 0.25f; o1.w *= 0.25f;
            }
            __stcs((float4*)(out + idx), o0);
            __stcs((float4*)(out + idx + 4), o1);
            __half2 hpack[4];
            #pragma unroll
            for (int j = 0; j < 4; j++)
                hpack[j] = __floats2half2_rn(dn * v[2 * j], dn * v[2 * j + 1]);
            __stcs((uint4*)(hdst + idx), *(uint4*)hpack);
        }
    }
}

// ---------------- launch --------------------------------------------------

extern "C" void kernel_launch(void* const* d_in, const int* in_sizes, int n_in,
                              void* d_out, int out_size) {
    const float* ue = (const float*)d_in[0];   // [NU, 64]
    const float* ie = (const float*)d_in[1];   // [NI, 64]
    const float* W  = (const float*)d_in[2];   // [3, 64, 64]
    const int*   ui = (const int*)d_in[3];     // [E]
    const int*   ii = (const int*)d_in[4];     // [E]
    float* out = (float*)d_out;                // [NN, 64]

    int E = in_sizes[3];
    if (E > EMAX) E = EMAX;

    int nScatter = (E + 255) / 256;
    int nInit    = (NN * DD / 2 + 255) / 256;

    k_hist<<<(E + 255) / 256, 256>>>(ui, ii, E);
    k_scan1<<<NB, 256>>>();
    k_scatterinit<<<nScatter + nInit, 256>>>(ui, ii, E, ue, ie, out, nScatter);

    for (int l = 0; l < LAYERS; l++) {
        k_layer<<<(NN + 127) / 128, 256>>>(W + l * 64 * 64, out, l & 1, l == LAYERS - 1);
    }
}

// round 9
// speedup vs baseline: 2.6095x; 1.2381x over previous
#include <cuda_runtime.h>
#include <cuda_fp16.h>
#include <cuda_bf16.h>

#define NU     100000
#define NI     50000
#define NN     150000          // NU + NI
#define DD     64
#define EMAX   3000000
#define LAYERS 3
#define NB     ((NN + 255) / 256)   // 586 scan blocks
#define ROWB   128                  // bytes per fp16 row

// ---------------- static device scratch (no allocations allowed) ----------
__device__ int   g_deg[NN];              // zero-init; re-zeroed by k_scan1 every run
__device__ int   g_rowptr[NN + 1];
__device__ int   g_cursor[NN];
__device__ int   g_bsum[NB];
__device__ int   g_flag[NB];             // zero-init; reset by k_scatterinit every run
__device__ int   g_colidx[2 * EMAX];     // BYTE offsets (node*128), 24 MB
__device__ float g_dis[NN];
__device__ __align__(128) __half g_h[2 * NN * DD];   // double-buffered fp16 h'

// ---------------- CSR build ----------------------------------------------

__global__ void k_hist(const int* __restrict__ ui, const int* __restrict__ ii, int E) {
    int e = blockIdx.x * blockDim.x + threadIdx.x;
    if (e < E) {
        atomicAdd(&g_deg[__ldcs(ui + e)], 1);
        atomicAdd(&g_deg[NU + __ldcs(ii + e)], 1);
    }
}

// single-launch decoupled scan; also zeroes g_deg for the next replay.
__global__ void __launch_bounds__(256) k_scan1() {
    __shared__ int wsum[8];
    __shared__ int sboff;
    int t = threadIdx.x, b = blockIdx.x;
    int lane = t & 31, wid = t >> 5;
    int i = b * 256 + t;

    int d = 0;
    if (i < NN) { d = g_deg[i]; g_deg[i] = 0; }

    int inc = d;
    #pragma unroll
    for (int o = 1; o < 32; o <<= 1) {
        int x = __shfl_up_sync(0xffffffffu, inc, o);
        if (lane >= o) inc += x;
    }
    if (lane == 31) wsum[wid] = inc;
    if (t == 0) sboff = 0;
    __syncthreads();
    if (t == 0) {
        int run = 0;
        #pragma unroll
        for (int k = 0; k < 8; k++) { int v = wsum[k]; wsum[k] = run; run += v; }
        g_bsum[b] = run;
        __threadfence();
        atomicExch(&g_flag[b], 1);
    }
    __syncthreads();

    int acc = 0;
    for (int j = t; j < b; j += 256) {
        while (((volatile int*)g_flag)[j] == 0) { }
        __threadfence();
        acc += ((volatile int*)g_bsum)[j];
    }
    #pragma unroll
    for (int o = 16; o > 0; o >>= 1) acc += __shfl_down_sync(0xffffffffu, acc, o);
    if (lane == 0 && acc != 0) atomicAdd(&sboff, acc);
    __syncthreads();

    int off = sboff + wsum[wid] + inc - d;
    if (i < NN) {
        g_rowptr[i] = off;
        g_cursor[i] = off;
        g_dis[i]    = rsqrtf((float)d + 1e-10f);
        if (i == NN - 1) g_rowptr[NN] = off + d;
    }
}

// fused scatter (stores BYTE offsets node*128) + init; resets g_flag.
__global__ void __launch_bounds__(256) k_scatterinit(
        const int* __restrict__ ui, const int* __restrict__ ii, int E,
        const float* __restrict__ ue, const float* __restrict__ ie,
        float* __restrict__ out, int nScatter) {
    int b = blockIdx.x, t = threadIdx.x;
    if (b < nScatter) {
        int e = b * 256 + t;
        if (e < NB) g_flag[e] = 0;
        if (e < E) {
            int u  = __ldcs(ui + e);
            int it = NU + __ldcs(ii + e);
            int p1 = atomicAdd(&g_cursor[u], 1);
            g_colidx[p1] = it * ROWB;
            int p2 = atomicAdd(&g_cursor[it], 1);
            g_colidx[p2] = u * ROWB;
        }
    } else {
        int p = (b - nScatter) * 256 + t;
        if (p < NN * DD / 2) {
            int i = p * 2;
            int n = i >> 6;
            float2 x = (n < NU) ? *(const float2*)(ue + i)
                                : *(const float2*)(ie + i - NU * DD);
            __stcs((float2*)(out + i), x);
            float dn = g_dis[n];
            *(__half2*)(g_h + i) = __floats2half2_rn(dn * x.x, dn * x.y);
        }
    }
}

// accumulate 8 halves (one uint4) into 8 scalar fp32 accumulators
#define ACC8(raw)                                                          \
    do {                                                                   \
        float2 f_;                                                         \
        f_ = __half22float2(*(const __half2*)&(raw).x); a0 += f_.x; a1 += f_.y; \
        f_ = __half22float2(*((const __half2*)&(raw).x + 1)); a2 += f_.x; a3 += f_.y; \
        f_ = __half22float2(*(const __half2*)&(raw).z); a4 += f_.x; a5 += f_.y; \
        f_ = __half22float2(*((const __half2*)&(raw).z + 1)); a6 += f_.x; a7 += f_.y; \
    } while (0)

// ---------------- fused layer: gather(SpMM) -> 64x64 GEMM -> epilogue -----
// Gather: warp w -> rows w*16..w*16+15. Quarter-warps (8 lanes) each process
// one edge per step (4 edges/warp-step); lane loads 16B of the 128B fp16 row.
// Full 32-edge chunks are predicate-free and fully unrolled.
__global__ void __launch_bounds__(256) k_layer(const float* __restrict__ W,
                                               float* __restrict__ out,
                                               int parity, int last) {
    __shared__ float Ws[64 * 64];    // deswizzled: Ws[k*64 + hh*32 + g*4 + pos]
    __shared__ float As[128 * 68];

    const __half* __restrict__ hsrc = g_h + (size_t)parity * NN * DD;
    __half* __restrict__       hdst = g_h + (size_t)(parity ^ 1) * NN * DD;

    int t = threadIdx.x;
    int row0 = blockIdx.x * 128;
    int w = t >> 5, lane = t & 31;
    int q  = lane >> 3;            // quarter 0..3
    int ql = lane & 7;             // lane-in-quarter

    const char* hb = (const char*)hsrc + ql * 16;   // per-lane base

    for (int i = t; i < 4096; i += 256) {
        int col = i >> 6, k = i & 63;
        int g = col >> 3, hh = (col >> 2) & 1, pos = col & 3;
        Ws[k * 64 + hh * 32 + g * 4 + pos] = W[i];
    }

    for (int rr = 0; rr < 16; rr++) {
        int r = w * 16 + rr;
        int n = row0 + r;
        float a0 = 0.f, a1 = 0.f, a2 = 0.f, a3 = 0.f,
              a4 = 0.f, a5 = 0.f, a6 = 0.f, a7 = 0.f;
        if (n < NN) {
            int s = g_rowptr[n];
            int cnt = g_rowptr[n + 1] - s;
            int nfull = cnt & ~31;
            int base = s;
            // full chunks: no predicates, fixed unroll
            for (; base < s + nfull; base += 32) {
                int off = g_colidx[base + lane];
                #pragma unroll
                for (int j = 0; j < 32; j += 4) {
                    int mo = __shfl_sync(0xffffffffu, off, j + q);
                    uint4 raw = *(const uint4*)(hb + mo);
                    ACC8(raw);
                }
            }
            // ragged tail
            int rem = cnt - nfull;
            if (rem) {
                int off = 0;
                if (lane < rem) off = g_colidx[base + lane];
                for (int j = 0; j < rem; j += 4) {
                    int mo = __shfl_sync(0xffffffffu, off, j + q);
                    if (j + q < rem) {
                        uint4 raw = *(const uint4*)(hb + mo);
                        ACC8(raw);
                    }
                }
            }
        }
        // reduce across the 4 quarters (xor 8, then xor 16)
        a0 += __shfl_xor_sync(0xffffffffu, a0, 8);
        a1 += __shfl_xor_sync(0xffffffffu, a1, 8);
        a2 += __shfl_xor_sync(0xffffffffu, a2, 8);
        a3 += __shfl_xor_sync(0xffffffffu, a3, 8);
        a4 += __shfl_xor_sync(0xffffffffu, a4, 8);
        a5 += __shfl_xor_sync(0xffffffffu, a5, 8);
        a6 += __shfl_xor_sync(0xffffffffu, a6, 8);
        a7 += __shfl_xor_sync(0xffffffffu, a7, 8);
        a0 += __shfl_xor_sync(0xffffffffu, a0, 16);
        a1 += __shfl_xor_sync(0xffffffffu, a1, 16);
        a2 += __shfl_xor_sync(0xffffffffu, a2, 16);
        a3 += __shfl_xor_sync(0xffffffffu, a3, 16);
        a4 += __shfl_xor_sync(0xffffffffu, a4, 16);
        a5 += __shfl_xor_sync(0xffffffffu, a5, 16);
        a6 += __shfl_xor_sync(0xffffffffu, a6, 16);
        a7 += __shfl_xor_sync(0xffffffffu, a7, 16);
        if (q == 0) {
            float dn = (n < NN) ? g_dis[n] : 0.f;
            float4 v0 = make_float4(a0 * dn, a1 * dn, a2 * dn, a3 * dn);
            float4 v1 = make_float4(a4 * dn, a5 * dn, a6 * dn, a7 * dn);
            *(float4*)&As[r * 68 + ql * 8]     = v0;
            *(float4*)&As[r * 68 + ql * 8 + 4] = v1;
        }
    }
    __syncthreads();

    // GEMM: thread -> rows rb+{0,32,64,96}, cols g*8..g*8+7
    int rb = t >> 3;     // 0..31
    int g  = t & 7;      // 0..7
    float sum[4][8];
    #pragma unroll
    for (int m = 0; m < 4; m++)
        #pragma unroll
        for (int j = 0; j < 8; j++) sum[m][j] = 0.f;

    #pragma unroll 4
    for (int k = 0; k < 64; k++) {
        float4 w0 = *(const float4*)&Ws[k * 64 + g * 4];
        float4 w1 = *(const float4*)&Ws[k * 64 + 32 + g * 4];
        float b0 = As[(rb      ) * 68 + k];
        float b1 = As[(rb +  32) * 68 + k];
        float b2 = As[(rb +  64) * 68 + k];
        float b3 = As[(rb +  96) * 68 + k];
        sum[0][0] += b0 * w0.x; sum[0][1] += b0 * w0.y; sum[0][2] += b0 * w0.z; sum[0][3] += b0 * w0.w;
        sum[0][4] += b0 * w1.x; sum[0][5] += b0 * w1.y; sum[0][6] += b0 * w1.z; sum[0][7] += b0 * w1.w;
        sum[1][0] += b1 * w0.x; sum[1][1] += b1 * w0.y; sum[1][2] += b1 * w0.z; sum[1][3] += b1 * w0.w;
        sum[1][4] += b1 * w1.x; sum[1][5] += b1 * w1.y; sum[1][6] += b1 * w1.z; sum[1][7] += b1 * w1.w;
        sum[2][0] += b2 * w0.x; sum[2][1] += b2 * w0.y; sum[2][2] += b2 * w0.z; sum[2][3] += b2 * w0.w;
        sum[2][4] += b2 * w1.x; sum[2][5] += b2 * w1.y; sum[2][6] += b2 * w1.z; sum[2][7] += b2 * w1.w;
        sum[3][0] += b3 * w0.x; sum[3][1] += b3 * w0.y; sum[3][2] += b3 * w0.z; sum[3][3] += b3 * w0.w;
        sum[3][4] += b3 * w1.x; sum[3][5] += b3 * w1.y; sum[3][6] += b3 * w1.z; sum[3][7] += b3 * w1.w;
    }

    int c0 = g * 8;
    #pragma unroll
    for (int m = 0; m < 4; m++) {
        int n = row0 + rb + 32 * m;
        if (n < NN) {
            float dn = g_dis[n];
            int idx = n * 64 + c0;
            float4 o0 = __ldcs((const float4*)(out + idx));
            float4 o1 = __ldcs((const float4*)(out + idx + 4));
            float v[8];
            #pragma unroll
            for (int j = 0; j < 8; j++) v[j] = fmaxf(sum[m][j], 0.f);
            o0.x += v[0]; o0.y += v[1]; o0.z += v[2]; o0.w += v[3];
            o1.x += v[4]; o1.y += v[5]; o1.z += v[6]; o1.w += v[7];
            if (last) {
                o0.x *= 0.25f; o0.y *= 0.25f; o0.z *= 0.25f; o0.w *= 0.25f;
                o1.x *= 0.25f; o1.y *= 0.25f; o1.z *= 0.25f; o1.w *= 0.25f;
            }
            __stcs((float4*)(out + idx), o0);
            __stcs((float4*)(out + idx + 4), o1);
            __half2 hpack[4];
            #pragma unroll
            for (int j = 0; j < 4; j++)
                hpack[j] = __floats2half2_rn(dn * v[2 * j], dn * v[2 * j + 1]);
            __stcs((uint4*)(hdst + idx), *(uint4*)hpack);
        }
    }
}

// ---------------- launch --------------------------------------------------

extern "C" void kernel_launch(void* const* d_in, const int* in_sizes, int n_in,
                              void* d_out, int out_size) {
    const float* ue = (const float*)d_in[0];   // [NU, 64]
    const float* ie = (const float*)d_in[1];   // [NI, 64]
    const float* W  = (const float*)d_in[2];   // [3, 64, 64]
    const int*   ui = (const int*)d_in[3];     // [E]
    const int*   ii = (const int*)d_in[4];     // [E]
    float* out = (float*)d_out;                // [NN, 64]

    int E = in_sizes[3];
    if (E > EMAX) E = EMAX;

    int nScatter = (E + 255) / 256;
    int nInit    = (NN * DD / 2 + 255) / 256;

    k_hist<<<(E + 255) / 256, 256>>>(ui, ii, E);
    k_scan1<<<NB, 256>>>();
    k_scatterinit<<<nScatter + nInit, 256>>>(ui, ii, E, ue, ie, out, nScatter);

    for (int l = 0; l < LAYERS; l++) {
        k_layer<<<(NN + 127) / 128, 256>>>(W + l * 64 * 64, out, l & 1, l == LAYERS - 1);
    }
}

// round 11
// speedup vs baseline: 2.8981x; 1.1106x over previous
#include <cuda_runtime.h>
#include <cuda_fp16.h>
#include <cuda_bf16.h>
#include <cstdint>

#define NU     100000
#define NI     50000
#define NN     150000          // NU + NI
#define DD     64
#define EMAX   3000000
#define LAYERS 3
#define NB     ((NN + 255) / 256)   // 586 scan blocks
#define ROWB   128                  // bytes per fp16 row

// ---------------- static device scratch (no allocations allowed) ----------
__device__ int   g_deg[NN];              // zero-init; re-zeroed by k_scan1 every run
__device__ int   g_rowptr[NN + 1];
__device__ int   g_cursor[NN];
__device__ int   g_bsum[NB];
__device__ int   g_flag[NB];             // zero-init; reset by k_scatterinit every run
__device__ int   g_colidx[2 * EMAX];     // BYTE offsets (node*128), 24 MB
__device__ float g_dis[NN];
__device__ __align__(128) __half g_h[2 * NN * DD];   // double-buffered fp16 h'

// ---------------- CSR build ----------------------------------------------

__global__ void k_hist(const int* __restrict__ ui, const int* __restrict__ ii, int E) {
    int e = blockIdx.x * blockDim.x + threadIdx.x;
    if (e < E) {
        atomicAdd(&g_deg[__ldcs(ui + e)], 1);
        atomicAdd(&g_deg[NU + __ldcs(ii + e)], 1);
    }
}

__global__ void __launch_bounds__(256) k_scan1() {
    __shared__ int wsum[8];
    __shared__ int sboff;
    int t = threadIdx.x, b = blockIdx.x;
    int lane = t & 31, wid = t >> 5;
    int i = b * 256 + t;

    int d = 0;
    if (i < NN) { d = g_deg[i]; g_deg[i] = 0; }

    int inc = d;
    #pragma unroll
    for (int o = 1; o < 32; o <<= 1) {
        int x = __shfl_up_sync(0xffffffffu, inc, o);
        if (lane >= o) inc += x;
    }
    if (lane == 31) wsum[wid] = inc;
    if (t == 0) sboff = 0;
    __syncthreads();
    if (t == 0) {
        int run = 0;
        #pragma unroll
        for (int k = 0; k < 8; k++) { int v = wsum[k]; wsum[k] = run; run += v; }
        g_bsum[b] = run;
        __threadfence();
        atomicExch(&g_flag[b], 1);
    }
    __syncthreads();

    int acc = 0;
    for (int j = t; j < b; j += 256) {
        while (((volatile int*)g_flag)[j] == 0) { }
        __threadfence();
        acc += ((volatile int*)g_bsum)[j];
    }
    #pragma unroll
    for (int o = 16; o > 0; o >>= 1) acc += __shfl_down_sync(0xffffffffu, acc, o);
    if (lane == 0 && acc != 0) atomicAdd(&sboff, acc);
    __syncthreads();

    int off = sboff + wsum[wid] + inc - d;
    if (i < NN) {
        g_rowptr[i] = off;
        g_cursor[i] = off;
        g_dis[i]    = rsqrtf((float)d + 1e-10f);
        if (i == NN - 1) g_rowptr[NN] = off + d;
    }
}

__global__ void __launch_bounds__(256) k_scatterinit(
        const int* __restrict__ ui, const int* __restrict__ ii, int E,
        const float* __restrict__ ue, const float* __restrict__ ie,
        float* __restrict__ out, int nScatter) {
    int b = blockIdx.x, t = threadIdx.x;
    if (b < nScatter) {
        int e = b * 256 + t;
        if (e < NB) g_flag[e] = 0;
        if (e < E) {
            int u  = __ldcs(ui + e);
            int it = NU + __ldcs(ii + e);
            int p1 = atomicAdd(&g_cursor[u], 1);
            g_colidx[p1] = it * ROWB;
            int p2 = atomicAdd(&g_cursor[it], 1);
            g_colidx[p2] = u * ROWB;
        }
    } else {
        int p = (b - nScatter) * 256 + t;
        if (p < NN * DD / 2) {
            int i = p * 2;
            int n = i >> 6;
            float2 x = (n < NU) ? *(const float2*)(ue + i)
                                : *(const float2*)(ie + i - NU * DD);
            __stcs((float2*)(out + i), x);
            float dn = g_dis[n];
            *(__half2*)(g_h + i) = __floats2half2_rn(dn * x.x, dn * x.y);
        }
    }
}

// accumulate 8 halves (one uint4) into 8 scalar fp32 accumulators
#define ACC8(raw)                                                          \
    do {                                                                   \
        float2 f_;                                                         \
        f_ = __half22float2(*(const __half2*)&(raw).x); a0 += f_.x; a1 += f_.y; \
        f_ = __half22float2(*((const __half2*)&(raw).x + 1)); a2 += f_.x; a3 += f_.y; \
        f_ = __half22float2(*(const __half2*)&(raw).z); a4 += f_.x; a5 += f_.y; \
        f_ = __half22float2(*((const __half2*)&(raw).z + 1)); a6 += f_.x; a7 += f_.y; \
    } while (0)

#define MMA16816(d, a, b0_, b1_)                                            \
    asm volatile("mma.sync.aligned.m16n8k16.row.col.f32.f16.f16.f32 "       \
                 "{%0,%1,%2,%3},{%4,%5,%6,%7},{%8,%9},{%0,%1,%2,%3};"       \
                 : "+f"((d)[0]), "+f"((d)[1]), "+f"((d)[2]), "+f"((d)[3])   \
                 : "r"(a[0]), "r"(a[1]), "r"(a[2]), "r"(a[3]),              \
                   "r"(b0_), "r"(b1_))

// ---------------- fused layer: gather(SpMM) -> HMMA GEMM -> epilogue ------
// Gather: warp w -> rows w*16..w*16+15, quarter-warp LDG.128, writes fp16 As.
// GEMM: warp w computes its own 16 rows x 64 cols via mma.m16n8k16.
__global__ void __launch_bounds__(256) k_layer(const float* __restrict__ W,
                                               float* __restrict__ out,
                                               int parity, int last) {
    __shared__ __half AsH[128 * 72];   // stride 72 halves (144B): +16B skew/row
    __shared__ __half WsH[64 * 72];    // WsH[o*72 + k] = fp16(W[o][k])

    const __half* __restrict__ hsrc = g_h + (size_t)parity * NN * DD;
    __half* __restrict__       hdst = g_h + (size_t)(parity ^ 1) * NN * DD;

    int t = threadIdx.x;
    int row0 = blockIdx.x * 128;
    int w = t >> 5, lane = t & 31;
    int q  = lane >> 3;            // quarter 0..3
    int ql = lane & 7;             // lane-in-quarter
    int wrow = w * 16;

    const char* hb = (const char*)hsrc + ql * 16;   // per-lane base

    // stage W as fp16 rows [o][k]  (coalesced read, conflict-free write)
    for (int i = t; i < 4096; i += 256)
        WsH[(i >> 6) * 72 + (i & 63)] = __float2half(W[i]);

    // ---- gather phase ----
    for (int rr = 0; rr < 16; rr++) {
        int r = wrow + rr;
        int n = row0 + r;
        float a0 = 0.f, a1 = 0.f, a2 = 0.f, a3 = 0.f,
              a4 = 0.f, a5 = 0.f, a6 = 0.f, a7 = 0.f;
        if (n < NN) {
            int s = g_rowptr[n];
            int cnt = g_rowptr[n + 1] - s;
            int nfull = cnt & ~31;
            int base = s;
            for (; base < s + nfull; base += 32) {
                int off = g_colidx[base + lane];
                #pragma unroll
                for (int j = 0; j < 32; j += 4) {
                    int mo = __shfl_sync(0xffffffffu, off, j + q);
                    uint4 raw = *(const uint4*)(hb + mo);
                    ACC8(raw);
                }
            }
            int rem = cnt - nfull;
            if (rem) {
                int off = 0;
                if (lane < rem) off = g_colidx[base + lane];
                for (int j = 0; j < rem; j += 4) {
                    int mo = __shfl_sync(0xffffffffu, off, j + q);
                    if (j + q < rem) {
                        uint4 raw = *(const uint4*)(hb + mo);
                        ACC8(raw);
                    }
                }
            }
        }
        a0 += __shfl_xor_sync(0xffffffffu, a0, 8);
        a1 += __shfl_xor_sync(0xffffffffu, a1, 8);
        a2 += __shfl_xor_sync(0xffffffffu, a2, 8);
        a3 += __shfl_xor_sync(0xffffffffu, a3, 8);
        a4 += __shfl_xor_sync(0xffffffffu, a4, 8);
        a5 += __shfl_xor_sync(0xffffffffu, a5, 8);
        a6 += __shfl_xor_sync(0xffffffffu, a6, 8);
        a7 += __shfl_xor_sync(0xffffffffu, a7, 8);
        a0 += __shfl_xor_sync(0xffffffffu, a0, 16);
        a1 += __shfl_xor_sync(0xffffffffu, a1, 16);
        a2 += __shfl_xor_sync(0xffffffffu, a2, 16);
        a3 += __shfl_xor_sync(0xffffffffu, a3, 16);
        a4 += __shfl_xor_sync(0xffffffffu, a4, 16);
        a5 += __shfl_xor_sync(0xffffffffu, a5, 16);
        a6 += __shfl_xor_sync(0xffffffffu, a6, 16);
        a7 += __shfl_xor_sync(0xffffffffu, a7, 16);
        if (q == 0) {
            float dn = (n < NN) ? g_dis[n] : 0.f;
            __half2 p[4];
            p[0] = __floats2half2_rn(a0 * dn, a1 * dn);
            p[1] = __floats2half2_rn(a2 * dn, a3 * dn);
            p[2] = __floats2half2_rn(a4 * dn, a5 * dn);
            p[3] = __floats2half2_rn(a6 * dn, a7 * dn);
            *(uint4*)&AsH[r * 72 + ql * 8] = *(uint4*)p;
        }
    }
    __syncthreads();

    // ---- HMMA GEMM: warp w -> rows wrow..wrow+15, all 64 cols ----
    float d[8][4];
    #pragma unroll
    for (int i = 0; i < 8; i++)
        #pragma unroll
        for (int j = 0; j < 4; j++) d[i][j] = 0.f;

    #pragma unroll
    for (int kk = 0; kk < 64; kk += 16) {
        // A fragment 16x16: lanes 0-15 rows, +8 halves for k upper
        uint32_t a[4];
        {
            uint32_t addr = (uint32_t)__cvta_generic_to_shared(
                &AsH[(wrow + (lane & 15)) * 72 + kk + ((lane >> 4) << 3)]);
            asm volatile("ldmatrix.sync.aligned.m8n8.x4.shared.b16 {%0,%1,%2,%3}, [%4];"
                         : "=r"(a[0]), "=r"(a[1]), "=r"(a[2]), "=r"(a[3]) : "r"(addr));
        }
        #pragma unroll
        for (int nt16 = 0; nt16 < 4; nt16++) {
            // B fragments for two n8 tiles (rows of WsH = output cols)
            uint32_t b[4];
            int nrow = nt16 * 16 + ((lane & 16) >> 1) + (lane & 7);
            int kcol = kk + (lane & 8);
            uint32_t addr = (uint32_t)__cvta_generic_to_shared(&WsH[nrow * 72 + kcol]);
            asm volatile("ldmatrix.sync.aligned.m8n8.x4.shared.b16 {%0,%1,%2,%3}, [%4];"
                         : "=r"(b[0]), "=r"(b[1]), "=r"(b[2]), "=r"(b[3]) : "r"(addr));
            MMA16816(d[nt16 * 2],     a, b[0], b[1]);
            MMA16816(d[nt16 * 2 + 1], a, b[2], b[3]);
        }
    }

    // ---- epilogue ----
    int group = lane >> 2, t4 = lane & 3;
    int r1 = row0 + wrow + group;
    int r2 = r1 + 8;
    float dn1 = (r1 < NN) ? g_dis[r1] : 0.f;
    float dn2 = (r2 < NN) ? g_dis[r2] : 0.f;

    #pragma unroll
    for (int nt = 0; nt < 8; nt++) {
        int c = nt * 8 + t4 * 2;
        if (r1 < NN) {
            float v0 = fmaxf(d[nt][0], 0.f);
            float v1 = fmaxf(d[nt][1], 0.f);
            int idx = r1 * 64 + c;
            float2 o = __ldcs((const float2*)(out + idx));
            o.x += v0; o.y += v1;
            if (last) { o.x *= 0.25f; o.y *= 0.25f; }
            __stcs((float2*)(out + idx), o);
            __stcs((__half2*)(hdst + idx), __floats2half2_rn(dn1 * v0, dn1 * v1));
        }
        if (r2 < NN) {
            float v0 = fmaxf(d[nt][2], 0.f);
            float v1 = fmaxf(d[nt][3], 0.f);
            int idx = r2 * 64 + c;
            float2 o = __ldcs((const float2*)(out + idx));
            o.x += v0; o.y += v1;
            if (last) { o.x *= 0.25f; o.y *= 0.25f; }
            __stcs((float2*)(out + idx), o);
            __stcs((__half2*)(hdst + idx), __floats2half2_rn(dn2 * v0, dn2 * v1));
        }
    }
}

// ---------------- launch --------------------------------------------------

extern "C" void kernel_launch(void* const* d_in, const int* in_sizes, int n_in,
                              void* d_out, int out_size) {
    const float* ue = (const float*)d_in[0];   // [NU, 64]
    const float* ie = (const float*)d_in[1];   // [NI, 64]
    const float* W  = (const float*)d_in[2];   // [3, 64, 64]
    const int*   ui = (const int*)d_in[3];     // [E]
    const int*   ii = (const int*)d_in[4];     // [E]
    float* out = (float*)d_out;                // [NN, 64]

    int E = in_sizes[3];
    if (E > EMAX) E = EMAX;

    int nScatter = (E + 255) / 256;
    int nInit    = (NN * DD / 2 + 255) / 256;

    k_hist<<<(E + 255) / 256, 256>>>(ui, ii, E);
    k_scan1<<<NB, 256>>>();
    k_scatterinit<<<nScatter + nInit, 256>>>(ui, ii, E, ue, ie, out, nScatter);

    for (int l = 0; l < LAYERS; l++) {
        k_layer<<<(NN + 127) / 128, 256>>>(W + l * 64 * 64, out, l & 1, l == LAYERS - 1);
    }
}

// round 12
// speedup vs baseline: 3.0580x; 1.0552x over previous
#include <cuda_runtime.h>
#include <cuda_fp16.h>
#include <cuda_bf16.h>
#include <cstdint>

#define NU     100000
#define NI     50000
#define NN     150000          // NU + NI
#define DD     64
#define EMAX   3000000
#define LAYERS 3
#define NB     ((NN + 255) / 256)   // 586 scan blocks
#define ROWB   128                  // bytes per fp16 row

// ---------------- static device scratch (no allocations allowed) ----------
__device__ int   g_deg[NN];              // zero-init; re-zeroed by k_scan1 every run
__device__ int   g_rowptr[NN + 1];
__device__ int   g_cursor[NN];
__device__ int   g_bsum[NB];
__device__ int   g_flag[NB];             // zero-init; reset by k_scatterinit every run
__device__ int   g_colidx[2 * EMAX];     // BYTE offsets (node*128), 24 MB
__device__ float g_dis[NN];
__device__ __align__(128) __half g_h[2 * NN * DD];   // double-buffered fp16 h'

// ---------------- CSR build ----------------------------------------------

__global__ void k_hist(const int* __restrict__ ui, const int* __restrict__ ii, int E) {
    int e = blockIdx.x * blockDim.x + threadIdx.x;
    if (e < E) {
        atomicAdd(&g_deg[__ldcs(ui + e)], 1);
        atomicAdd(&g_deg[NU + __ldcs(ii + e)], 1);
    }
}

__global__ void __launch_bounds__(256) k_scan1() {
    __shared__ int wsum[8];
    __shared__ int sboff;
    int t = threadIdx.x, b = blockIdx.x;
    int lane = t & 31, wid = t >> 5;
    int i = b * 256 + t;

    int d = 0;
    if (i < NN) { d = g_deg[i]; g_deg[i] = 0; }

    int inc = d;
    #pragma unroll
    for (int o = 1; o < 32; o <<= 1) {
        int x = __shfl_up_sync(0xffffffffu, inc, o);
        if (lane >= o) inc += x;
    }
    if (lane == 31) wsum[wid] = inc;
    if (t == 0) sboff = 0;
    __syncthreads();
    if (t == 0) {
        int run = 0;
        #pragma unroll
        for (int k = 0; k < 8; k++) { int v = wsum[k]; wsum[k] = run; run += v; }
        g_bsum[b] = run;
        __threadfence();
        atomicExch(&g_flag[b], 1);
    }
    __syncthreads();

    int acc = 0;
    for (int j = t; j < b; j += 256) {
        while (((volatile int*)g_flag)[j] == 0) { }
        __threadfence();
        acc += ((volatile int*)g_bsum)[j];
    }
    #pragma unroll
    for (int o = 16; o > 0; o >>= 1) acc += __shfl_down_sync(0xffffffffu, acc, o);
    if (lane == 0 && acc != 0) atomicAdd(&sboff, acc);
    __syncthreads();

    int off = sboff + wsum[wid] + inc - d;
    if (i < NN) {
        g_rowptr[i] = off;
        g_cursor[i] = off;
        g_dis[i]    = rsqrtf((float)d + 1e-10f);
        if (i == NN - 1) g_rowptr[NN] = off + d;
    }
}

__global__ void __launch_bounds__(256) k_scatterinit(
        const int* __restrict__ ui, const int* __restrict__ ii, int E,
        const float* __restrict__ ue, const float* __restrict__ ie,
        float* __restrict__ out, int nScatter) {
    int b = blockIdx.x, t = threadIdx.x;
    if (b < nScatter) {
        int e = b * 256 + t;
        if (e < NB) g_flag[e] = 0;
        if (e < E) {
            int u  = __ldcs(ui + e);
            int it = NU + __ldcs(ii + e);
            int p1 = atomicAdd(&g_cursor[u], 1);
            g_colidx[p1] = it * ROWB;
            int p2 = atomicAdd(&g_cursor[it], 1);
            g_colidx[p2] = u * ROWB;
        }
    } else {
        int p = (b - nScatter) * 256 + t;
        if (p < NN * DD / 2) {
            int i = p * 2;
            int n = i >> 6;
            float2 x = (n < NU) ? *(const float2*)(ue + i)
                                : *(const float2*)(ie + i - NU * DD);
            __stcs((float2*)(out + i), x);
            float dn = g_dis[n];
            *(__half2*)(g_h + i) = __floats2half2_rn(dn * x.x, dn * x.y);
        }
    }
}

// pairwise: r0+r1 in fp16 (4 HADD2), then convert+accumulate to fp32
#define ACCPAIR(r0, r1)                                                     \
    do {                                                                    \
        __half2 h0_ = __hadd2(*(const __half2*)&(r0).x, *(const __half2*)&(r1).x); \
        __half2 h1_ = __hadd2(*((const __half2*)&(r0).x + 1), *((const __half2*)&(r1).x + 1)); \
        __half2 h2_ = __hadd2(*(const __half2*)&(r0).z, *(const __half2*)&(r1).z); \
        __half2 h3_ = __hadd2(*((const __half2*)&(r0).z + 1), *((const __half2*)&(r1).z + 1)); \
        float2 f_;                                                          \
        f_ = __half22float2(h0_); a0 += f_.x; a1 += f_.y;                   \
        f_ = __half22float2(h1_); a2 += f_.x; a3 += f_.y;                   \
        f_ = __half22float2(h2_); a4 += f_.x; a5 += f_.y;                   \
        f_ = __half22float2(h3_); a6 += f_.x; a7 += f_.y;                   \
    } while (0)

// single-edge accumulate (tail odd case)
#define ACC8(raw)                                                          \
    do {                                                                   \
        float2 f_;                                                         \
        f_ = __half22float2(*(const __half2*)&(raw).x); a0 += f_.x; a1 += f_.y; \
        f_ = __half22float2(*((const __half2*)&(raw).x + 1)); a2 += f_.x; a3 += f_.y; \
        f_ = __half22float2(*(const __half2*)&(raw).z); a4 += f_.x; a5 += f_.y; \
        f_ = __half22float2(*((const __half2*)&(raw).z + 1)); a6 += f_.x; a7 += f_.y; \
    } while (0)

#define MMA16816(d, a, b0_, b1_)                                            \
    asm volatile("mma.sync.aligned.m16n8k16.row.col.f32.f16.f16.f32 "       \
                 "{%0,%1,%2,%3},{%4,%5,%6,%7},{%8,%9},{%0,%1,%2,%3};"       \
                 : "+f"((d)[0]), "+f"((d)[1]), "+f"((d)[2]), "+f"((d)[3])   \
                 : "r"(a[0]), "r"(a[1]), "r"(a[2]), "r"(a[3]),              \
                   "r"(b0_), "r"(b1_))

// ---------------- fused layer: gather(SpMM) -> HMMA GEMM -> epilogue ------
__global__ void __launch_bounds__(256, 5) k_layer(const float* __restrict__ W,
                                                  float* __restrict__ out,
                                                  int parity, int last) {
    __shared__ __half AsH[128 * 72];   // stride 72 halves (144B): +16B skew/row
    __shared__ __half WsH[64 * 72];    // WsH[o*72 + k] = fp16(W[o][k])

    const __half* __restrict__ hsrc = g_h + (size_t)parity * NN * DD;
    __half* __restrict__       hdst = g_h + (size_t)(parity ^ 1) * NN * DD;

    int t = threadIdx.x;
    int row0 = blockIdx.x * 128;
    int w = t >> 5, lane = t & 31;
    int q  = lane >> 3;            // quarter 0..3
    int ql = lane & 7;             // lane-in-quarter
    int wrow = w * 16;

    const char* hb = (const char*)hsrc + ql * 16;   // per-lane base

    for (int i = t; i < 4096; i += 256)
        WsH[(i >> 6) * 72 + (i & 63)] = __float2half(W[i]);

    // ---- gather phase: warp w -> rows wrow..wrow+15, quarter-warp LDG.128,
    // two edges pre-summed in fp16 (HADD2) before fp32 accumulate ----
    for (int rr = 0; rr < 16; rr++) {
        int r = wrow + rr;
        int n = row0 + r;
        float a0 = 0.f, a1 = 0.f, a2 = 0.f, a3 = 0.f,
              a4 = 0.f, a5 = 0.f, a6 = 0.f, a7 = 0.f;
        if (n < NN) {
            int s = g_rowptr[n];
            int cnt = g_rowptr[n + 1] - s;
            int nfull = cnt & ~31;
            int base = s;
            // full 32-edge chunks: predicate-free, pairwise
            for (; base < s + nfull; base += 32) {
                int off = g_colidx[base + lane];
                #pragma unroll
                for (int j = 0; j < 32; j += 8) {
                    int mo0 = __shfl_sync(0xffffffffu, off, j + q);
                    int mo1 = __shfl_sync(0xffffffffu, off, j + q + 4);
                    uint4 r0 = *(const uint4*)(hb + mo0);
                    uint4 r1 = *(const uint4*)(hb + mo1);
                    ACCPAIR(r0, r1);
                }
            }
            // ragged tail: pairwise with per-pair predicates
            int rem = cnt - nfull;
            if (rem) {
                int off = 0;
                if (lane < rem) off = g_colidx[base + lane];
                for (int j = 0; j < rem; j += 8) {
                    int e0 = j + q, e1 = j + q + 4;
                    int mo0 = __shfl_sync(0xffffffffu, off, e0);
                    int mo1 = __shfl_sync(0xffffffffu, off, e1);
                    if (e1 < rem) {
                        uint4 r0 = *(const uint4*)(hb + mo0);
                        uint4 r1 = *(const uint4*)(hb + mo1);
                        ACCPAIR(r0, r1);
                    } else if (e0 < rem) {
                        uint4 r0 = *(const uint4*)(hb + mo0);
                        ACC8(r0);
                    }
                }
            }
        }
        a0 += __shfl_xor_sync(0xffffffffu, a0, 8);
        a1 += __shfl_xor_sync(0xffffffffu, a1, 8);
        a2 += __shfl_xor_sync(0xffffffffu, a2, 8);
        a3 += __shfl_xor_sync(0xffffffffu, a3, 8);
        a4 += __shfl_xor_sync(0xffffffffu, a4, 8);
        a5 += __shfl_xor_sync(0xffffffffu, a5, 8);
        a6 += __shfl_xor_sync(0xffffffffu, a6, 8);
        a7 += __shfl_xor_sync(0xffffffffu, a7, 8);
        a0 += __shfl_xor_sync(0xffffffffu, a0, 16);
        a1 += __shfl_xor_sync(0xffffffffu, a1, 16);
        a2 += __shfl_xor_sync(0xffffffffu, a2, 16);
        a3 += __shfl_xor_sync(0xffffffffu, a3, 16);
        a4 += __shfl_xor_sync(0xffffffffu, a4, 16);
        a5 += __shfl_xor_sync(0xffffffffu, a5, 16);
        a6 += __shfl_xor_sync(0xffffffffu, a6, 16);
        a7 += __shfl_xor_sync(0xffffffffu, a7, 16);
        if (q == 0) {
            float dn = (n < NN) ? g_dis[n] : 0.f;
            __half2 p[4];
            p[0] = __floats2half2_rn(a0 * dn, a1 * dn);
            p[1] = __floats2half2_rn(a2 * dn, a3 * dn);
            p[2] = __floats2half2_rn(a4 * dn, a5 * dn);
            p[3] = __floats2half2_rn(a6 * dn, a7 * dn);
            *(uint4*)&AsH[r * 72 + ql * 8] = *(uint4*)p;
        }
    }
    __syncthreads();

    // ---- HMMA GEMM: warp w -> rows wrow..wrow+15, all 64 cols ----
    float d[8][4];
    #pragma unroll
    for (int i = 0; i < 8; i++)
        #pragma unroll
        for (int j = 0; j < 4; j++) d[i][j] = 0.f;

    #pragma unroll
    for (int kk = 0; kk < 64; kk += 16) {
        uint32_t a[4];
        {
            uint32_t addr = (uint32_t)__cvta_generic_to_shared(
                &AsH[(wrow + (lane & 15)) * 72 + kk + ((lane >> 4) << 3)]);
            asm volatile("ldmatrix.sync.aligned.m8n8.x4.shared.b16 {%0,%1,%2,%3}, [%4];"
                         : "=r"(a[0]), "=r"(a[1]), "=r"(a[2]), "=r"(a[3]) : "r"(addr));
        }
        #pragma unroll
        for (int nt16 = 0; nt16 < 4; nt16++) {
            uint32_t b[4];
            int nrow = nt16 * 16 + ((lane & 16) >> 1) + (lane & 7);
            int kcol = kk + (lane & 8);
            uint32_t addr = (uint32_t)__cvta_generic_to_shared(&WsH[nrow * 72 + kcol]);
            asm volatile("ldmatrix.sync.aligned.m8n8.x4.shared.b16 {%0,%1,%2,%3}, [%4];"
                         : "=r"(b[0]), "=r"(b[1]), "=r"(b[2]), "=r"(b[3]) : "r"(addr));
            MMA16816(d[nt16 * 2],     a, b[0], b[1]);
            MMA16816(d[nt16 * 2 + 1], a, b[2], b[3]);
        }
    }

    // ---- epilogue ----
    int group = lane >> 2, t4 = lane & 3;
    int r1 = row0 + wrow + group;
    int r2 = r1 + 8;
    float dn1 = (r1 < NN) ? g_dis[r1] : 0.f;
    float dn2 = (r2 < NN) ? g_dis[r2] : 0.f;

    #pragma unroll
    for (int nt = 0; nt < 8; nt++) {
        int c = nt * 8 + t4 * 2;
        if (r1 < NN) {
            float v0 = fmaxf(d[nt][0], 0.f);
            float v1 = fmaxf(d[nt][1], 0.f);
            int idx = r1 * 64 + c;
            float2 o = __ldcs((const float2*)(out + idx));
            o.x += v0; o.y += v1;
            if (last) { o.x *= 0.25f; o.y *= 0.25f; }
            __stcs((float2*)(out + idx), o);
            __stcs((__half2*)(hdst + idx), __floats2half2_rn(dn1 * v0, dn1 * v1));
        }
        if (r2 < NN) {
            float v0 = fmaxf(d[nt][2], 0.f);
            float v1 = fmaxf(d[nt][3], 0.f);
            int idx = r2 * 64 + c;
            float2 o = __ldcs((const float2*)(out + idx));
            o.x += v0; o.y += v1;
            if (last) { o.x *= 0.25f; o.y *= 0.25f; }
            __stcs((float2*)(out + idx), o);
            __stcs((__half2*)(hdst + idx), __floats2half2_rn(dn2 * v0, dn2 * v1));
        }
    }
}

// ---------------- launch --------------------------------------------------

extern "C" void kernel_launch(void* const* d_in, const int* in_sizes, int n_in,
                              void* d_out, int out_size) {
    const float* ue = (const float*)d_in[0];   // [NU, 64]
    const float* ie = (const float*)d_in[1];   // [NI, 64]
    const float* W  = (const float*)d_in[2];   // [3, 64, 64]
    const int*   ui = (const int*)d_in[3];     // [E]
    const int*   ii = (const int*)d_in[4];     // [E]
    float* out = (float*)d_out;                // [NN, 64]

    int E = in_sizes[3];
    if (E > EMAX) E = EMAX;

    int nScatter = (E + 255) / 256;
    int nInit    = (NN * DD / 2 + 255) / 256;

    k_hist<<<(E + 255) / 256, 256>>>(ui, ii, E);
    k_scan1<<<NB, 256>>>();
    k_scatterinit<<<nScatter + nInit, 256>>>(ui, ii, E, ue, ie, out, nScatter);

    for (int l = 0; l < LAYERS; l++) {
        k_layer<<<(NN + 127) / 128, 256>>>(W + l * 64 * 64, out, l & 1, l == LAYERS - 1);
    }
}

// round 13
// speedup vs baseline: 3.4034x; 1.1129x over previous
#include <cuda_runtime.h>
#include <cuda_fp16.h>
#include <cuda_bf16.h>
#include <cstdint>

#define NU     100000
#define NI     50000
#define NN     150000          // NU + NI
#define DD     64
#define EMAX   3000000
#define LAYERS 3
#define NB     ((NN + 255) / 256)   // 586 scan blocks
#define ROWB   128                  // bytes per fp16 row
#define BUFSZ  ((NN + 1) * DD)      // buffer stride incl. zero dummy row

// ---------------- static device scratch (no allocations allowed) ----------
__device__ int   g_deg[NN];              // zero-init; re-zeroed by k_scan1 every run
__device__ int   g_rowptr[NN + 1];
__device__ int   g_cursor[NN];
__device__ int   g_bsum[NB];
__device__ int   g_flag[NB];             // zero-init; reset by k_scatterinit every run
__device__ int   g_colidx[2 * EMAX];     // BYTE offsets (node*128), 24 MB
__device__ float g_dis[NN];
// double-buffered fp16 h'; row NN of each buffer is a dummy ZERO row that is
// never written (static zero-init) -> predicate-free padded gathers.
__device__ __align__(128) __half g_h[2 * BUFSZ];

// ---------------- CSR build ----------------------------------------------

__global__ void k_hist(const int* __restrict__ ui, const int* __restrict__ ii, int E) {
    int e = blockIdx.x * blockDim.x + threadIdx.x;
    if (e < E) {
        atomicAdd(&g_deg[__ldcs(ui + e)], 1);
        atomicAdd(&g_deg[NU + __ldcs(ii + e)], 1);
    }
}

__global__ void __launch_bounds__(256) k_scan1() {
    __shared__ int wsum[8];
    __shared__ int sboff;
    int t = threadIdx.x, b = blockIdx.x;
    int lane = t & 31, wid = t >> 5;
    int i = b * 256 + t;

    int d = 0;
    if (i < NN) { d = g_deg[i]; g_deg[i] = 0; }

    int inc = d;
    #pragma unroll
    for (int o = 1; o < 32; o <<= 1) {
        int x = __shfl_up_sync(0xffffffffu, inc, o);
        if (lane >= o) inc += x;
    }
    if (lane == 31) wsum[wid] = inc;
    if (t == 0) sboff = 0;
    __syncthreads();
    if (t == 0) {
        int run = 0;
        #pragma unroll
        for (int k = 0; k < 8; k++) { int v = wsum[k]; wsum[k] = run; run += v; }
        g_bsum[b] = run;
        __threadfence();
        atomicExch(&g_flag[b], 1);
    }
    __syncthreads();

    int acc = 0;
    for (int j = t; j < b; j += 256) {
        while (((volatile int*)g_flag)[j] == 0) { }
        __threadfence();
        acc += ((volatile int*)g_bsum)[j];
    }
    #pragma unroll
    for (int o = 16; o > 0; o >>= 1) acc += __shfl_down_sync(0xffffffffu, acc, o);
    if (lane == 0 && acc != 0) atomicAdd(&sboff, acc);
    __syncthreads();

    int off = sboff + wsum[wid] + inc - d;
    if (i < NN) {
        g_rowptr[i] = off;
        g_cursor[i] = off;
        g_dis[i]    = rsqrtf((float)d + 1e-10f);
        if (i == NN - 1) g_rowptr[NN] = off + d;
    }
}

__global__ void __launch_bounds__(256) k_scatterinit(
        const int* __restrict__ ui, const int* __restrict__ ii, int E,
        const float* __restrict__ ue, const float* __restrict__ ie,
        float* __restrict__ out, int nScatter) {
    int b = blockIdx.x, t = threadIdx.x;
    if (b < nScatter) {
        int e = b * 256 + t;
        if (e < NB) g_flag[e] = 0;
        if (e < E) {
            int u  = __ldcs(ui + e);
            int it = NU + __ldcs(ii + e);
            int p1 = atomicAdd(&g_cursor[u], 1);
            g_colidx[p1] = it * ROWB;
            int p2 = atomicAdd(&g_cursor[it], 1);
            g_colidx[p2] = u * ROWB;
        }
    } else {
        int p = (b - nScatter) * 256 + t;
        if (p < NN * DD / 2) {
            int i = p * 2;
            int n = i >> 6;
            float2 x = (n < NU) ? *(const float2*)(ue + i)
                                : *(const float2*)(ie + i - NU * DD);
            __stcs((float2*)(out + i), x);
            float dn = g_dis[n];
            *(__half2*)(g_h + i) = __floats2half2_rn(dn * x.x, dn * x.y);
        }
    }
}

// convert 4 half2 (one padded uint4 view) and accumulate into fp32
#define CVTACC(h0_, h1_, h2_, h3_)                                          \
    do {                                                                    \
        float2 f_;                                                          \
        f_ = __half22float2(h0_); a0 += f_.x; a1 += f_.y;                   \
        f_ = __half22float2(h1_); a2 += f_.x; a3 += f_.y;                   \
        f_ = __half22float2(h2_); a4 += f_.x; a5 += f_.y;                   \
        f_ = __half22float2(h3_); a6 += f_.x; a7 += f_.y;                   \
    } while (0)

// pair step: 8 edges, predicate-free
#define PAIRSTEP(jbase)                                                     \
    do {                                                                    \
        int mo0_ = __shfl_sync(0xffffffffu, off, (jbase) + q);              \
        int mo1_ = __shfl_sync(0xffffffffu, off, (jbase) + q + 4);          \
        uint4 r0_ = *(const uint4*)(hb + mo0_);                             \
        uint4 r1_ = *(const uint4*)(hb + mo1_);                             \
        __half2 h0_ = __hadd2(*(const __half2*)&r0_.x, *(const __half2*)&r1_.x); \
        __half2 h1_ = __hadd2(*((const __half2*)&r0_.x + 1), *((const __half2*)&r1_.x + 1)); \
        __half2 h2_ = __hadd2(*(const __half2*)&r0_.z, *(const __half2*)&r1_.z); \
        __half2 h3_ = __hadd2(*((const __half2*)&r0_.z + 1), *((const __half2*)&r1_.z + 1)); \
        CVTACC(h0_, h1_, h2_, h3_);                                         \
    } while (0)

// quad step: 16 edges, predicate-free, two fp16 tree levels
#define QUADSTEP(jbase)                                                     \
    do {                                                                    \
        int mo0_ = __shfl_sync(0xffffffffu, off, (jbase) + q);              \
        int mo1_ = __shfl_sync(0xffffffffu, off, (jbase) + q + 4);          \
        int mo2_ = __shfl_sync(0xffffffffu, off, (jbase) + q + 8);          \
        int mo3_ = __shfl_sync(0xffffffffu, off, (jbase) + q + 12);         \
        uint4 r0_ = *(const uint4*)(hb + mo0_);                             \
        uint4 r1_ = *(const uint4*)(hb + mo1_);                             \
        uint4 r2_ = *(const uint4*)(hb + mo2_);                             \
        uint4 r3_ = *(const uint4*)(hb + mo3_);                             \
        __half2 pa0_ = __hadd2(*(const __half2*)&r0_.x, *(const __half2*)&r1_.x); \
        __half2 pa1_ = __hadd2(*((const __half2*)&r0_.x + 1), *((const __half2*)&r1_.x + 1)); \
        __half2 pa2_ = __hadd2(*(const __half2*)&r0_.z, *(const __half2*)&r1_.z); \
        __half2 pa3_ = __hadd2(*((const __half2*)&r0_.z + 1), *((const __half2*)&r1_.z + 1)); \
        __half2 pb0_ = __hadd2(*(const __half2*)&r2_.x, *(const __half2*)&r3_.x); \
        __half2 pb1_ = __hadd2(*((const __half2*)&r2_.x + 1), *((const __half2*)&r3_.x + 1)); \
        __half2 pb2_ = __hadd2(*(const __half2*)&r2_.z, *(const __half2*)&r3_.z); \
        __half2 pb3_ = __hadd2(*((const __half2*)&r2_.z + 1), *((const __half2*)&r3_.z + 1)); \
        __half2 q0_ = __hadd2(pa0_, pb0_);                                  \
        __half2 q1_ = __hadd2(pa1_, pb1_);                                  \
        __half2 q2_ = __hadd2(pa2_, pb2_);                                  \
        __half2 q3_ = __hadd2(pa3_, pb3_);                                  \
        CVTACC(q0_, q1_, q2_, q3_);                                         \
    } while (0)

#define MMA16816(d, a, b0_, b1_)                                            \
    asm volatile("mma.sync.aligned.m16n8k16.row.col.f32.f16.f16.f32 "       \
                 "{%0,%1,%2,%3},{%4,%5,%6,%7},{%8,%9},{%0,%1,%2,%3};"       \
                 : "+f"((d)[0]), "+f"((d)[1]), "+f"((d)[2]), "+f"((d)[3])   \
                 : "r"(a[0]), "r"(a[1]), "r"(a[2]), "r"(a[3]),              \
                   "r"(b0_), "r"(b1_))

// ---------------- fused layer: gather(SpMM) -> HMMA GEMM -> epilogue ------
// 128 threads / 64 rows per block. Warp w -> rows w*16..w*16+15.
__global__ void __launch_bounds__(128, 8) k_layer(const float* __restrict__ W,
                                                  float* __restrict__ out,
                                                  int parity, int last) {
    __shared__ __half AsH[64 * 72];    // stride 72 halves: +16B skew/row
    __shared__ __half WsH[64 * 72];    // WsH[o*72 + k] = fp16(W[o][k])

    const __half* __restrict__ hsrc = g_h + (size_t)parity * BUFSZ;
    __half* __restrict__       hdst = g_h + (size_t)(parity ^ 1) * BUFSZ;

    int t = threadIdx.x;
    int row0 = blockIdx.x * 64;
    int w = t >> 5, lane = t & 31;
    int q  = lane >> 3;            // quarter 0..3
    int ql = lane & 7;             // lane-in-quarter
    int wrow = w * 16;

    const char* hb = (const char*)hsrc + ql * 16;   // per-lane base

    for (int i = t; i < 4096; i += 128)
        WsH[(i >> 6) * 72 + (i & 63)] = __float2half(W[i]);

    // ---- gather phase: predicate-free via zero-row padding ----
    for (int rr = 0; rr < 16; rr++) {
        int r = wrow + rr;
        int n = row0 + r;
        float a0 = 0.f, a1 = 0.f, a2 = 0.f, a3 = 0.f,
              a4 = 0.f, a5 = 0.f, a6 = 0.f, a7 = 0.f;
        if (n < NN) {
            int s  = g_rowptr[n];
            int e_ = g_rowptr[n + 1];
            for (int base = s; base < e_; base += 32) {
                int cnt2 = e_ - base; if (cnt2 > 32) cnt2 = 32;
                int off = (lane < cnt2) ? g_colidx[base + lane] : (NN * ROWB);
                int cntp = (cnt2 + 7) & ~7;          // pad to multiple of 8
                int nq = cntp & ~15;                 // full 16-edge groups
                for (int j = 0; j < nq; j += 16) QUADSTEP(j);
                if (cntp & 8) PAIRSTEP(nq);
            }
        }
        a0 += __shfl_xor_sync(0xffffffffu, a0, 8);
        a1 += __shfl_xor_sync(0xffffffffu, a1, 8);
        a2 += __shfl_xor_sync(0xffffffffu, a2, 8);
        a3 += __shfl_xor_sync(0xffffffffu, a3, 8);
        a4 += __shfl_xor_sync(0xffffffffu, a4, 8);
        a5 += __shfl_xor_sync(0xffffffffu, a5, 8);
        a6 += __shfl_xor_sync(0xffffffffu, a6, 8);
        a7 += __shfl_xor_sync(0xffffffffu, a7, 8);
        a0 += __shfl_xor_sync(0xffffffffu, a0, 16);
        a1 += __shfl_xor_sync(0xffffffffu, a1, 16);
        a2 += __shfl_xor_sync(0xffffffffu, a2, 16);
        a3 += __shfl_xor_sync(0xffffffffu, a3, 16);
        a4 += __shfl_xor_sync(0xffffffffu, a4, 16);
        a5 += __shfl_xor_sync(0xffffffffu, a5, 16);
        a6 += __shfl_xor_sync(0xffffffffu, a6, 16);
        a7 += __shfl_xor_sync(0xffffffffu, a7, 16);
        if (q == 0) {
            float dn = (n < NN) ? g_dis[n] : 0.f;
            __half2 p[4];
            p[0] = __floats2half2_rn(a0 * dn, a1 * dn);
            p[1] = __floats2half2_rn(a2 * dn, a3 * dn);
            p[2] = __floats2half2_rn(a4 * dn, a5 * dn);
            p[3] = __floats2half2_rn(a6 * dn, a7 * dn);
            *(uint4*)&AsH[r * 72 + ql * 8] = *(uint4*)p;
        }
    }
    __syncthreads();

    // ---- HMMA GEMM: warp w -> rows wrow..wrow+15, all 64 cols ----
    float d[8][4];
    #pragma unroll
    for (int i = 0; i < 8; i++)
        #pragma unroll
        for (int j = 0; j < 4; j++) d[i][j] = 0.f;

    #pragma unroll
    for (int kk = 0; kk < 64; kk += 16) {
        uint32_t a[4];
        {
            uint32_t addr = (uint32_t)__cvta_generic_to_shared(
                &AsH[(wrow + (lane & 15)) * 72 + kk + ((lane >> 4) << 3)]);
            asm volatile("ldmatrix.sync.aligned.m8n8.x4.shared.b16 {%0,%1,%2,%3}, [%4];"
                         : "=r"(a[0]), "=r"(a[1]), "=r"(a[2]), "=r"(a[3]) : "r"(addr));
        }
        #pragma unroll
        for (int nt16 = 0; nt16 < 4; nt16++) {
            uint32_t b[4];
            int nrow = nt16 * 16 + ((lane & 16) >> 1) + (lane & 7);
            int kcol = kk + (lane & 8);
            uint32_t addr = (uint32_t)__cvta_generic_to_shared(&WsH[nrow * 72 + kcol]);
            asm volatile("ldmatrix.sync.aligned.m8n8.x4.shared.b16 {%0,%1,%2,%3}, [%4];"
                         : "=r"(b[0]), "=r"(b[1]), "=r"(b[2]), "=r"(b[3]) : "r"(addr));
            MMA16816(d[nt16 * 2],     a, b[0], b[1]);
            MMA16816(d[nt16 * 2 + 1], a, b[2], b[3]);
        }
    }

    // ---- epilogue ----
    int group = lane >> 2, t4 = lane & 3;
    int r1 = row0 + wrow + group;
    int r2 = r1 + 8;
    float dn1 = (r1 < NN) ? g_dis[r1] : 0.f;
    float dn2 = (r2 < NN) ? g_dis[r2] : 0.f;

    #pragma unroll
    for (int nt = 0; nt < 8; nt++) {
        int c = nt * 8 + t4 * 2;
        if (r1 < NN) {
            float v0 = fmaxf(d[nt][0], 0.f);
            float v1 = fmaxf(d[nt][1], 0.f);
            int idx = r1 * 64 + c;
            float2 o = __ldcs((const float2*)(out + idx));
            o.x += v0; o.y += v1;
            if (last) { o.x *= 0.25f; o.y *= 0.25f; }
            __stcs((float2*)(out + idx), o);
            __stcs((__half2*)(hdst + idx), __floats2half2_rn(dn1 * v0, dn1 * v1));
        }
        if (r2 < NN) {
            float v0 = fmaxf(d[nt][2], 0.f);
            float v1 = fmaxf(d[nt][3], 0.f);
            int idx = r2 * 64 + c;
            float2 o = __ldcs((const float2*)(out + idx));
            o.x += v0; o.y += v1;
            if (last) { o.x *= 0.25f; o.y *= 0.25f; }
            __stcs((float2*)(out + idx), o);
            __stcs((__half2*)(hdst + idx), __floats2half2_rn(dn2 * v0, dn2 * v1));
        }
    }
}

// ---------------- launch --------------------------------------------------

extern "C" void kernel_launch(void* const* d_in, const int* in_sizes, int n_in,
                              void* d_out, int out_size) {
    const float* ue = (const float*)d_in[0];   // [NU, 64]
    const float* ie = (const float*)d_in[1];   // [NI, 64]
    const float* W  = (const float*)d_in[2];   // [3, 64, 64]
    const int*   ui = (const int*)d_in[3];     // [E]
    const int*   ii = (const int*)d_in[4];     // [E]
    float* out = (float*)d_out;                // [NN, 64]

    int E = in_sizes[3];
    if (E > EMAX) E = EMAX;

    int nScatter = (E + 255) / 256;
    int nInit    = (NN * DD / 2 + 255) / 256;

    k_hist<<<(E + 255) / 256, 256>>>(ui, ii, E);
    k_scan1<<<NB, 256>>>();
    k_scatterinit<<<nScatter + nInit, 256>>>(ui, ii, E, ue, ie, out, nScatter);

    for (int l = 0; l < LAYERS; l++) {
        k_layer<<<(NN + 63) / 64, 128>>>(W + l * 64 * 64, out, l & 1, l == LAYERS - 1);
    }
}

// round 15
// speedup vs baseline: 4.0202x; 1.1812x over previous
#include <cuda_runtime.h>
#include <cuda_fp16.h>
#include <cuda_bf16.h>
#include <cstdint>

#define NU     100000
#define NI     50000
#define NN     150000          // NU + NI
#define DD     64
#define EMAX   3000000
#define LAYERS 3
#define NB     ((NN + 255) / 256)   // 586 scan blocks
#define ROWB   128                  // bytes per fp16 row
#define BUFSZ  ((NN + 1) * DD)      // buffer stride incl. zero dummy row

// ---------------- static device scratch (no allocations allowed) ----------
__device__ int   g_deg[NN];              // zero-init; re-zeroed by k_scan1 every run
__device__ int   g_rowptr[NN + 1];
__device__ int   g_cursor[NN];
__device__ int   g_bsum[NB];
__device__ int   g_flag[NB];             // zero-init; reset by k_scatterinit every run
__device__ int   g_colidx[2 * EMAX];     // BYTE offsets (node*128), 24 MB
__device__ float g_dis[NN];
// double-buffered fp16 h'; row NN of each buffer is a dummy ZERO row that is
// never written (static zero-init) -> predicate-free padded gathers.
__device__ __align__(128) __half g_h[2 * BUFSZ];

// ---------------- CSR build ----------------------------------------------

__global__ void k_hist(const int* __restrict__ ui, const int* __restrict__ ii, int E) {
    int e = blockIdx.x * blockDim.x + threadIdx.x;
    if (e < E) {
        atomicAdd(&g_deg[__ldcs(ui + e)], 1);
        atomicAdd(&g_deg[NU + __ldcs(ii + e)], 1);
    }
}

__global__ void __launch_bounds__(256) k_scan1() {
    __shared__ int wsum[8];
    __shared__ int sboff;
    int t = threadIdx.x, b = blockIdx.x;
    int lane = t & 31, wid = t >> 5;
    int i = b * 256 + t;

    int d = 0;
    if (i < NN) { d = g_deg[i]; g_deg[i] = 0; }

    int inc = d;
    #pragma unroll
    for (int o = 1; o < 32; o <<= 1) {
        int x = __shfl_up_sync(0xffffffffu, inc, o);
        if (lane >= o) inc += x;
    }
    if (lane == 31) wsum[wid] = inc;
    if (t == 0) sboff = 0;
    __syncthreads();
    if (t == 0) {
        int run = 0;
        #pragma unroll
        for (int k = 0; k < 8; k++) { int v = wsum[k]; wsum[k] = run; run += v; }
        g_bsum[b] = run;
        __threadfence();
        atomicExch(&g_flag[b], 1);
    }
    __syncthreads();

    int acc = 0;
    for (int j = t; j < b; j += 256) {
        while (((volatile int*)g_flag)[j] == 0) { }
        __threadfence();
        acc += ((volatile int*)g_bsum)[j];
    }
    #pragma unroll
    for (int o = 16; o > 0; o >>= 1) acc += __shfl_down_sync(0xffffffffu, acc, o);
    if (lane == 0 && acc != 0) atomicAdd(&sboff, acc);
    __syncthreads();

    int off = sboff + wsum[wid] + inc - d;
    if (i < NN) {
        g_rowptr[i] = off;
        g_cursor[i] = off;
        g_dis[i]    = rsqrtf((float)d + 1e-10f);
        if (i == NN - 1) g_rowptr[NN] = off + d;
    }
}

__global__ void __launch_bounds__(256) k_scatterinit(
        const int* __restrict__ ui, const int* __restrict__ ii, int E,
        const float* __restrict__ ue, const float* __restrict__ ie,
        float* __restrict__ out, int nScatter) {
    int b = blockIdx.x, t = threadIdx.x;
    if (b < nScatter) {
        int e = b * 256 + t;
        if (e < NB) g_flag[e] = 0;
        if (e < E) {
            int u  = __ldcs(ui + e);
            int it = NU + __ldcs(ii + e);
            int p1 = atomicAdd(&g_cursor[u], 1);
            g_colidx[p1] = it * ROWB;
            int p2 = atomicAdd(&g_cursor[it], 1);
            g_colidx[p2] = u * ROWB;
        }
    } else {
        int p = (b - nScatter) * 256 + t;
        if (p < NN * DD / 2) {
            int i = p * 2;
            int n = i >> 6;
            float2 x = (n < NU) ? *(const float2*)(ue + i)
                                : *(const float2*)(ie + i - NU * DD);
            __stcs((float2*)(out + i), x);
            float dn = g_dis[n];
            *(__half2*)(g_h + i) = __floats2half2_rn(dn * x.x, dn * x.y);
        }
    }
}

// convert 4 half2 and accumulate into fp32
#define CVTACC(h0_, h1_, h2_, h3_)                                          \
    do {                                                                    \
        float2 f_;                                                          \
        f_ = __half22float2(h0_); a0 += f_.x; a1 += f_.y;                   \
        f_ = __half22float2(h1_); a2 += f_.x; a3 += f_.y;                   \
        f_ = __half22float2(h2_); a4 += f_.x; a5 += f_.y;                   \
        f_ = __half22float2(h3_); a6 += f_.x; a7 += f_.y;                   \
    } while (0)

// pair step: 8 edges, predicate-free
#define PAIRSTEP(jbase)                                                     \
    do {                                                                    \
        int mo0_ = __shfl_sync(0xffffffffu, off, (jbase) + q);              \
        int mo1_ = __shfl_sync(0xffffffffu, off, (jbase) + q + 4);          \
        uint4 r0_ = *(const uint4*)(hb + mo0_);                             \
        uint4 r1_ = *(const uint4*)(hb + mo1_);                             \
        __half2 h0_ = __hadd2(*(const __half2*)&r0_.x, *(const __half2*)&r1_.x); \
        __half2 h1_ = __hadd2(*((const __half2*)&r0_.x + 1), *((const __half2*)&r1_.x + 1)); \
        __half2 h2_ = __hadd2(*(const __half2*)&r0_.z, *(const __half2*)&r1_.z); \
        __half2 h3_ = __hadd2(*((const __half2*)&r0_.z + 1), *((const __half2*)&r1_.z + 1)); \
        CVTACC(h0_, h1_, h2_, h3_);                                         \
    } while (0)

// quad step: 16 edges, predicate-free, two fp16 tree levels
#define QUADSTEP(jbase)                                                     \
    do {                                                                    \
        int mo0_ = __shfl_sync(0xffffffffu, off, (jbase) + q);              \
        int mo1_ = __shfl_sync(0xffffffffu, off, (jbase) + q + 4);          \
        int mo2_ = __shfl_sync(0xffffffffu, off, (jbase) + q + 8);          \
        int mo3_ = __shfl_sync(0xffffffffu, off, (jbase) + q + 12);         \
        uint4 r0_ = *(const uint4*)(hb + mo0_);                             \
        uint4 r1_ = *(const uint4*)(hb + mo1_);                             \
        uint4 r2_ = *(const uint4*)(hb + mo2_);                             \
        uint4 r3_ = *(const uint4*)(hb + mo3_);                             \
        __half2 pa0_ = __hadd2(*(const __half2*)&r0_.x, *(const __half2*)&r1_.x); \
        __half2 pa1_ = __hadd2(*((const __half2*)&r0_.x + 1), *((const __half2*)&r1_.x + 1)); \
        __half2 pa2_ = __hadd2(*(const __half2*)&r0_.z, *(const __half2*)&r1_.z); \
        __half2 pa3_ = __hadd2(*((const __half2*)&r0_.z + 1), *((const __half2*)&r1_.z + 1)); \
        __half2 pb0_ = __hadd2(*(const __half2*)&r2_.x, *(const __half2*)&r3_.x); \
        __half2 pb1_ = __hadd2(*((const __half2*)&r2_.x + 1), *((const __half2*)&r3_.x + 1)); \
        __half2 pb2_ = __hadd2(*(const __half2*)&r2_.z, *(const __half2*)&r3_.z); \
        __half2 pb3_ = __hadd2(*((const __half2*)&r2_.z + 1), *((const __half2*)&r3_.z + 1)); \
        __half2 q0_ = __hadd2(pa0_, pb0_);                                  \
        __half2 q1_ = __hadd2(pa1_, pb1_);                                  \
        __half2 q2_ = __hadd2(pa2_, pb2_);                                  \
        __half2 q3_ = __hadd2(pa3_, pb3_);                                  \
        CVTACC(q0_, q1_, q2_, q3_);                                         \
    } while (0)

#define H2SHFLX(v, m)                                                       \
    __halves2half2(__ushort_as_half((unsigned short)(__shfl_xor_sync(0xffffffffu, __half2_as_uint_lo(v), m))), __ushort_as_half(0))
// (helper above unused; reductions done via uint reinterpret below)

#define MMA16816(d, a, b0_, b1_)                                            \
    asm volatile("mma.sync.aligned.m16n8k16.row.col.f32.f16.f16.f32 "       \
                 "{%0,%1,%2,%3},{%4,%5,%6,%7},{%8,%9},{%0,%1,%2,%3};"       \
                 : "+f"((d)[0]), "+f"((d)[1]), "+f"((d)[2]), "+f"((d)[3])   \
                 : "r"(a[0]), "r"(a[1]), "r"(a[2]), "r"(a[3]),              \
                   "r"(b0_), "r"(b1_))

__device__ __forceinline__ __half2 h2_shflxor_add(__half2 v, int m) {
    uint32_t u = *(uint32_t*)&v;
    uint32_t o = __shfl_xor_sync(0xffffffffu, u, m);
    return __hadd2(v, *(__half2*)&o);
}

// ---------------- fused layer: gather(SpMM) -> HMMA GEMM -> epilogue ------
// 128 threads / 64 rows per block. Warp w -> rows w*16..w*16+15.
// Gather walks the warp's chunk stream with one-chunk colidx lookahead.
__global__ void __launch_bounds__(128, 8) k_layer(const float* __restrict__ W,
                                                  float* __restrict__ out,
                                                  int parity, int last) {
    __shared__ __half AsH[64 * 72];    // stride 72 halves: +16B skew/row
    __shared__ __half WsH[64 * 72];    // WsH[o*72 + k] = fp16(W[o][k])

    const __half* __restrict__ hsrc = g_h + (size_t)parity * BUFSZ;
    __half* __restrict__       hdst = g_h + (size_t)(parity ^ 1) * BUFSZ;

    int t = threadIdx.x;
    int row0 = blockIdx.x * 64;
    int w = t >> 5, lane = t & 31;
    int q  = lane >> 3;            // quarter 0..3
    int ql = lane & 7;             // lane-in-quarter
    int wrow = w * 16;

    const char* hb = (const char*)hsrc + ql * 16;   // per-lane base

    for (int i = t; i < 4096; i += 128)
        WsH[(i >> 6) * 72 + (i & 63)] = __float2half(W[i]);

    // rowptr for this warp's 17 boundaries, loaded once
    int n0 = row0 + wrow;
    int rpv = 0;
    {
        int idx = n0 + lane;
        if (idx > NN) idx = NN;
        if (lane < 17) rpv = g_rowptr[idx];
    }

    // ---- pipelined gather over the warp's flat chunk stream ----
    float a0 = 0.f, a1 = 0.f, a2 = 0.f, a3 = 0.f,
          a4 = 0.f, a5 = 0.f, a6 = 0.f, a7 = 0.f;
    int rr   = 0;
    int base = __shfl_sync(0xffffffffu, rpv, 0);
    int eC   = __shfl_sync(0xffffffffu, rpv, 1);
    int cnt  = eC - base; if (cnt > 32) cnt = 32;
    int off  = NN * ROWB;
    if (lane < cnt) off = g_colidx[base + lane];

    while (true) {
        // locate next chunk (possibly in a later row); warp-uniform control
        int nrr = rr, nbase = base + 32, neC = eC;
        while (nrr < 16 && nbase >= neC) {
            nrr++;
            if (nrr < 16) {
                nbase = __shfl_sync(0xffffffffu, rpv, nrr);
                neC   = __shfl_sync(0xffffffffu, rpv, nrr + 1);
            }
        }
        // prefetch next chunk's colidx (overlaps current chunk's compute)
        int ncnt = 0;
        int noff = NN * ROWB;
        if (nrr < 16) {
            ncnt = neC - nbase; if (ncnt > 32) ncnt = 32;
            if (lane < ncnt) noff = g_colidx[nbase + lane];
        }
        // process current chunk (padded, predicate-free)
        if (cnt > 0) {
            int cntp = (cnt + 7) & ~7;
            int nq = cntp & ~15;
            for (int j = 0; j < nq; j += 16) QUADSTEP(j);
            if (cntp & 8) PAIRSTEP(nq);
        }
        // row boundary: finish current row + any skipped empty rows
        if (nrr != rr) {
            {
                int n = n0 + rr;
                float dn = (n < NN) ? g_dis[n] : 0.f;
                __half2 p0 = __floats2half2_rn(a0, a1);
                __half2 p1 = __floats2half2_rn(a2, a3);
                __half2 p2 = __floats2half2_rn(a4, a5);
                __half2 p3 = __floats2half2_rn(a6, a7);
                p0 = h2_shflxor_add(p0, 8);  p1 = h2_shflxor_add(p1, 8);
                p2 = h2_shflxor_add(p2, 8);  p3 = h2_shflxor_add(p3, 8);
                p0 = h2_shflxor_add(p0, 16); p1 = h2_shflxor_add(p1, 16);
                p2 = h2_shflxor_add(p2, 16); p3 = h2_shflxor_add(p3, 16);
                if (q == 0) {
                    __half2 dn2 = __float2half2_rn(dn);
                    __half2 v[4];
                    v[0] = __hmul2(p0, dn2); v[1] = __hmul2(p1, dn2);
                    v[2] = __hmul2(p2, dn2); v[3] = __hmul2(p3, dn2);
                    *(uint4*)&AsH[(wrow + rr) * 72 + ql * 8] = *(uint4*)v;
                }
                a0 = a1 = a2 = a3 = a4 = a5 = a6 = a7 = 0.f;
            }
            for (int rz = rr + 1; rz < nrr; rz++) {
                if (q == 0) {
                    uint4 z = make_uint4(0u, 0u, 0u, 0u);
                    *(uint4*)&AsH[(wrow + rz) * 72 + ql * 8] = z;
                }
            }
        }
        if (nrr >= 16) break;
        rr = nrr; base = nbase; eC = neC; cnt = ncnt; off = noff;
    }
    __syncthreads();

    // ---- HMMA GEMM: warp w -> rows wrow..wrow+15, all 64 cols ----
    float d[8][4];
    #pragma unroll
    for (int i = 0; i < 8; i++)
        #pragma unroll
        for (int j = 0; j < 4; j++) d[i][j] = 0.f;

    #pragma unroll
    for (int kk = 0; kk < 64; kk += 16) {
        uint32_t a[4];
        {
            uint32_t addr = (uint32_t)__cvta_generic_to_shared(
                &AsH[(wrow + (lane & 15)) * 72 + kk + ((lane >> 4) << 3)]);
            asm volatile("ldmatrix.sync.aligned.m8n8.x4.shared.b16 {%0,%1,%2,%3}, [%4];"
                         : "=r"(a[0]), "=r"(a[1]), "=r"(a[2]), "=r"(a[3]) : "r"(addr));
        }
        #pragma unroll
        for (int nt16 = 0; nt16 < 4; nt16++) {
            uint32_t b[4];
            int nrow = nt16 * 16 + ((lane & 16) >> 1) + (lane & 7);
            int kcol = kk + (lane & 8);
            uint32_t addr = (uint32_t)__cvta_generic_to_shared(&WsH[nrow * 72 + kcol]);
            asm volatile("ldmatrix.sync.aligned.m8n8.x4.shared.b16 {%0,%1,%2,%3}, [%4];"
                         : "=r"(b[0]), "=r"(b[1]), "=r"(b[2]), "=r"(b[3]) : "r"(addr));
            MMA16816(d[nt16 * 2],     a, b[0], b[1]);
            MMA16816(d[nt16 * 2 + 1], a, b[2], b[3]);
        }
    }

    // ---- epilogue ----
    int group = lane >> 2, t4 = lane & 3;
    int r1 = row0 + wrow + group;
    int r2 = r1 + 8;
    float dn1 = (r1 < NN) ? g_dis[r1] : 0.f;
    float dn2 = (r2 < NN) ? g_dis[r2] : 0.f;

    #pragma unroll
    for (int nt = 0; nt < 8; nt++) {
        int c = nt * 8 + t4 * 2;
        if (r1 < NN) {
            float v0 = fmaxf(d[nt][0], 0.f);
            float v1 = fmaxf(d[nt][1], 0.f);
            int idx = r1 * 64 + c;
            float2 o = __ldcs((const float2*)(out + idx));
            o.x += v0; o.y += v1;
            if (last) { o.x *= 0.25f; o.y *= 0.25f; }
            __stcs((float2*)(out + idx), o);
            __stcs((__half2*)(hdst + idx), __floats2half2_rn(dn1 * v0, dn1 * v1));
        }
        if (r2 < NN) {
            float v0 = fmaxf(d[nt][2], 0.f);
            float v1 = fmaxf(d[nt][3], 0.f);
            int idx = r2 * 64 + c;
            float2 o = __ldcs((const float2*)(out + idx));
            o.x += v0; o.y += v1;
            if (last) { o.x *= 0.25f; o.y *= 0.25f; }
            __stcs((float2*)(out + idx), o);
            __stcs((__half2*)(hdst + idx), __floats2half2_rn(dn2 * v0, dn2 * v1));
        }
    }
}

// ---------------- launch --------------------------------------------------

extern "C" void kernel_launch(void* const* d_in, const int* in_sizes, int n_in,
                              void* d_out, int out_size) {
    const float* ue = (const float*)d_in[0];   // [NU, 64]
    const float* ie = (const float*)d_in[1];   // [NI, 64]
    const float* W  = (const float*)d_in[2];   // [3, 64, 64]
    const int*   ui = (const int*)d_in[3];     // [E]
    const int*   ii = (const int*)d_in[4];     // [E]
    float* out = (float*)d_out;                // [NN, 64]

    int E = in_sizes[3];
    if (E > EMAX) E = EMAX;

    int nScatter = (E + 255) / 256;
    int nInit    = (NN * DD / 2 + 255) / 256;

    k_hist<<<(E + 255) / 256, 256>>>(ui, ii, E);
    k_scan1<<<NB, 256>>>();
    k_scatterinit<<<nScatter + nInit, 256>>>(ui, ii, E, ue, ie, out, nScatter);

    for (int l = 0; l < LAYERS; l++) {
        k_layer<<<(NN + 63) / 64, 128>>>(W + l * 64 * 64, out, l & 1, l == LAYERS - 1);
    }
}